// round 8
// baseline (speedup 1.0000x reference)
#include <cuda_runtime.h>
#include <cuda_bf16.h>
#include <math.h>
#include <stdint.h>

// Problem constants
#define B_  8
#define S_  1024
#define D_  512
#define H_  8
#define DH  64
#define FF_ 2048
#define L_  6
#define M_  (B_*S_)   // 8192 rows

// Transposed-weight layout (bf16 hi/lo), per layer:
#define OFF_QKV 0
#define OFF_FC  786432
#define OFF_W1  1048576
#define OFF_W2  2097152
#define WT_L    3145728
#define WT_TOT  (WT_L*L_)

// ---------------- scratch (static device globals; no allocation) ----------------
__device__ float g_x[M_*D_];                 // fp32 activations (residual stream)
__device__ float g_t[M_*D_];                 // pre-LN temp
__device__ unsigned short g_qh[M_*3*D_], g_ql[M_*3*D_]; // qkv bf16 hi/lo
__device__ unsigned short g_xh[M_*D_],  g_xl[M_*D_];    // x bf16 hi/lo
__device__ unsigned short g_ah[M_*D_],  g_al[M_*D_];    // attention out bf16 hi/lo
__device__ unsigned short g_hh[M_*FF_], g_hl[M_*FF_];   // ffn hidden bf16 hi/lo
__device__ unsigned short g_wth[WT_TOT], g_wtl[WT_TOT]; // transposed weights bf16 hi/lo
__device__ int g_pos[M_];

// ============================================================================
// helpers (baseline sm_80+ PTX only — no tcgen05 on this toolchain target)
// ============================================================================
__device__ __forceinline__ uint32_t su32(const void* p) {
    uint32_t a;
    asm("{ .reg .u64 t; cvta.to.shared.u64 t, %1; cvt.u32.u64 %0, t; }"
        : "=r"(a) : "l"(p));
    return a;
}

__device__ __forceinline__ void cp16(uint32_t s, const void* g) {
    asm volatile("cp.async.cg.shared.global [%0], [%1], 16;" :: "r"(s), "l"(g) : "memory");
}

__device__ __forceinline__ void ldsm4(uint32_t* r, uint32_t addr) {
    asm volatile("ldmatrix.sync.aligned.m8n8.x4.shared.b16 {%0,%1,%2,%3}, [%4];"
        : "=r"(r[0]), "=r"(r[1]), "=r"(r[2]), "=r"(r[3]) : "r"(addr));
}

__device__ __forceinline__ void ldsm4t(uint32_t* r, uint32_t addr) {
    asm volatile("ldmatrix.sync.aligned.m8n8.x4.trans.shared.b16 {%0,%1,%2,%3}, [%4];"
        : "=r"(r[0]), "=r"(r[1]), "=r"(r[2]), "=r"(r[3]) : "r"(addr));
}

__device__ __forceinline__ void mma_bf16(float* c, const uint32_t* a, const uint32_t* b) {
    asm volatile(
        "mma.sync.aligned.m16n8k16.row.col.f32.bf16.bf16.f32 "
        "{%0,%1,%2,%3}, {%4,%5,%6,%7}, {%8,%9}, {%0,%1,%2,%3};"
        : "+f"(c[0]), "+f"(c[1]), "+f"(c[2]), "+f"(c[3])
        : "r"(a[0]), "r"(a[1]), "r"(a[2]), "r"(a[3]), "r"(b[0]), "r"(b[1]));
}

__device__ __forceinline__ void bf16_split(float v, unsigned short& hi, unsigned short& lo) {
    __nv_bfloat16 h = __float2bfloat16(v);
    hi = __bfloat16_as_ushort(h);
    lo = __bfloat16_as_ushort(__float2bfloat16(v - __bfloat162float(h)));
}

// ============================================================================
// Position scan
// ============================================================================
__global__ void pos_scan_kernel(const int* __restrict__ mask)
{
    __shared__ int sc[S_];
    int b = blockIdx.x;
    int t = threadIdx.x;
    int v = (mask[b*S_ + t] != 0) ? 1 : 0;
    sc[t] = v;
    __syncthreads();
    for (int off = 1; off < S_; off <<= 1) {
        int add = (t >= off) ? sc[t - off] : 0;
        __syncthreads();
        sc[t] += add;
        __syncthreads();
    }
    g_pos[b*S_ + t] = v ? sc[t] : 0;
}

// ============================================================================
// x = x_in + sin_table[pos]; emit fp32 + bf16 hi/lo
// ============================================================================
__global__ void add_pos_kernel(const float* __restrict__ xin)
{
    int idx = blockIdx.x * 256 + threadIdx.x;
    int d = idx & (D_-1);
    int row = idx >> 9;
    int pos = g_pos[row];
    float e = 0.f;
    if (pos > 0) {
        const float c = -9.210340371976184f / 255.0f;
        if (d < 256) e = sinf((float)pos * expf((float)d * c));
        else         e = cosf((float)pos * expf((float)(d - 256) * c));
    }
    float v = xin[idx] + e;
    g_x[idx] = v;
    bf16_split(v, g_xh[idx], g_xl[idx]);
}

// ============================================================================
// Weight transpose + bf16 split: W[K,N] -> T_hi/T_lo [N,K]  (grid.z = layer)
// ============================================================================
__global__ void transpose_split_kernel(const float* __restrict__ W,
                                       unsigned short* __restrict__ Th,
                                       unsigned short* __restrict__ Tl,
                                       int K, int N, size_t out_off)
{
    __shared__ float t[32][33];
    int l = blockIdx.z;
    const float* Wp = W + (size_t)l * K * N;
    unsigned short* Thp = Th + (size_t)l * WT_L + out_off;
    unsigned short* Tlp = Tl + (size_t)l * WT_L + out_off;
    int n0 = blockIdx.x * 32, k0 = blockIdx.y * 32;
    int tx = threadIdx.x, ty = threadIdx.y;   // 32 x 8
    #pragma unroll
    for (int i = 0; i < 4; i++)
        t[ty + 8*i][tx] = Wp[(size_t)(k0 + ty + 8*i) * N + n0 + tx];
    __syncthreads();
    #pragma unroll
    for (int i = 0; i < 4; i++) {
        float v = t[tx][ty + 8*i];
        size_t o = (size_t)(n0 + ty + 8*i) * K + k0 + tx;
        bf16_split(v, Thp[o], Tlp[o]);
    }
}

// ============================================================================
// mma.sync bf16 GEMM: C[M,N] = A[M,K] @ B^T (B given as [N,K] bf16 hi/lo rows)
// 3-term split AhBh + AhBl + AlBh, fp32 accum.
// CTA 128x128, BK=32, 256 thr, 8 warps (2x4) of 64x32.
// 3-stage cp.async pipeline, ONE __syncthreads per chunk.
// EPI: 0 = fp32 out; 1 = +bias +Res fp32 out; 2 = relu(+bias) -> bf16 hi/lo;
//      3 = plain -> bf16 hi/lo
// ============================================================================
#define BK 32
#define ROW_B 80            // smem row stride bytes (40 bf16, conflict-free)
#define TEN_B 10240         // 128 rows * 80B
#define STG_B (4*TEN_B)     // 4 tensors per stage
#define NSTG 3

template<int EPI>
__global__ void __launch_bounds__(256)
gemm_mma(const unsigned short* __restrict__ Ah, const unsigned short* __restrict__ Al,
         const unsigned short* __restrict__ Bh, const unsigned short* __restrict__ Bl,
         const float* __restrict__ bias, const float* __restrict__ Res,
         float* __restrict__ Cf,
         unsigned short* __restrict__ Ch, unsigned short* __restrict__ Cl,
         int N, int K)
{
    extern __shared__ __align__(16) char smem[];
    const uint32_t sb = su32(smem);
    const int tid = threadIdx.x;
    const int lane = tid & 31, wid = tid >> 5;
    const int wm = wid & 1, wn = wid >> 1;
    const int m0 = blockIdx.y * 128, n0 = blockIdx.x * 128;

    float acc[4][4][4];
    #pragma unroll
    for (int i = 0; i < 4; i++)
        #pragma unroll
        for (int j = 0; j < 4; j++)
            #pragma unroll
            for (int k = 0; k < 4; k++) acc[i][j][k] = 0.f;

    const int nc = K / BK;

    auto load_chunk = [&](int c, int stage) {
        const uint32_t st = sb + stage * STG_B;
        const int k0 = c * BK;
        #pragma unroll
        for (int j = 0; j < 2; j++) {
            int idx = tid * 2 + j;          // 0..511
            int r = idx >> 2, sg = idx & 3;
            uint32_t so = r * ROW_B + sg * 16;
            const size_t ga = (size_t)(m0 + r) * K + k0 + sg * 8;
            const size_t gb = (size_t)(n0 + r) * K + k0 + sg * 8;
            cp16(st +           so, Ah + ga);
            cp16(st +   TEN_B + so, Al + ga);
            cp16(st + 2*TEN_B + so, Bh + gb);
            cp16(st + 3*TEN_B + so, Bl + gb);
        }
        asm volatile("cp.async.commit_group;" ::: "memory");
    };

    auto compute_chunk = [&](int stage) {
        const uint32_t st = sb + stage * STG_B;
        const uint32_t lrow = (lane & 15);
        const uint32_t lcol = (lane >> 4) * 16;
        #pragma unroll
        for (int ks = 0; ks < 2; ks++) {
            const uint32_t kb = ks * 32 + lcol;
            uint32_t aH[4][4], aL[4][4], bH[4][2], bL[4][2];
            #pragma unroll
            for (int mt = 0; mt < 4; mt++) {
                uint32_t ad = st + (wm*64 + mt*16 + lrow) * ROW_B + kb;
                ldsm4(aH[mt], ad);
                ldsm4(aL[mt], ad + TEN_B);
            }
            #pragma unroll
            for (int g = 0; g < 2; g++) {
                uint32_t bd = st + 2*TEN_B + (wn*32 + g*16 + lrow) * ROW_B + kb;
                uint32_t t0[4], t1[4];
                ldsm4(t0, bd);
                ldsm4(t1, bd + TEN_B);
                bH[g*2][0] = t0[0]; bH[g*2][1] = t0[2];
                bH[g*2+1][0] = t0[1]; bH[g*2+1][1] = t0[3];
                bL[g*2][0] = t1[0]; bL[g*2][1] = t1[2];
                bL[g*2+1][0] = t1[1]; bL[g*2+1][1] = t1[3];
            }
            #pragma unroll
            for (int mt = 0; mt < 4; mt++)
                #pragma unroll
                for (int nt = 0; nt < 4; nt++) {
                    mma_bf16(acc[mt][nt], aH[mt], bH[nt]);
                    mma_bf16(acc[mt][nt], aH[mt], bL[nt]);
                    mma_bf16(acc[mt][nt], aL[mt], bH[nt]);
                }
        }
    };

    // 3-stage pipeline, depth-2 prefetch, one sync per chunk
    load_chunk(0, 0);
    if (nc > 1) load_chunk(1, 1);
    for (int c = 0; c < nc; c++) {
        if (c + 1 < nc)
            asm volatile("cp.async.wait_group 1;" ::: "memory");
        else
            asm volatile("cp.async.wait_group 0;" ::: "memory");
        __syncthreads();
        if (c + 2 < nc) load_chunk(c + 2, (c + 2) % NSTG);
        compute_chunk(c % NSTG);
    }

    // ---- epilogue ----
    const int r0 = lane >> 2;
    const int cp = (lane & 3) * 2;
    #pragma unroll
    for (int mt = 0; mt < 4; mt++) {
        #pragma unroll
        for (int half = 0; half < 2; half++) {
            const size_t row = (size_t)(m0 + wm*64 + mt*16 + half*8 + r0);
            #pragma unroll
            for (int nt = 0; nt < 4; nt++) {
                const int col = n0 + wn*32 + nt*8 + cp;
                float v0 = acc[mt][nt][half*2 + 0];
                float v1 = acc[mt][nt][half*2 + 1];
                if (EPI == 0) {
                    float2 o; o.x = v0; o.y = v1;
                    *(float2*)&Cf[row*N + col] = o;
                } else if (EPI == 1) {
                    float2 bb = *(const float2*)&bias[col];
                    float2 rr = *(const float2*)&Res[row*N + col];
                    float2 o; o.x = v0 + bb.x + rr.x; o.y = v1 + bb.y + rr.y;
                    *(float2*)&Cf[row*N + col] = o;
                } else {
                    if (EPI == 2) {
                        float2 bb = *(const float2*)&bias[col];
                        v0 = fmaxf(v0 + bb.x, 0.f);
                        v1 = fmaxf(v1 + bb.y, 0.f);
                    }
                    ushort2 hh, ll;
                    bf16_split(v0, hh.x, ll.x);
                    bf16_split(v1, hh.y, ll.y);
                    *(ushort2*)&Ch[row*N + col] = hh;
                    *(ushort2*)&Cl[row*N + col] = ll;
                }
            }
        }
    }
}

// ============================================================================
// Flash attention via mma.sync bf16 (hi/lo split, 3-term): scale = 1.
// DIRECT-EXP softmax: p = exp(s) in fp32 (no running max; |s| is O(10) here),
// row-sum l accumulated in registers, single normalization at the end.
// CTA: 128 q-rows x full S keys (64-key tiles). 256 thr, warps 4(m) x 2(n).
// ============================================================================
#define AST 144                 // smem row stride bytes (64 bf16 + 16B pad)
#define A_QH 0
#define A_QL 18432
#define A_KH 36864              // + stage*9216
#define A_KL 55296
#define A_VH 73728
#define A_VL 92160
#define A_PH 110592             // single-buffered (sync-protected)
#define A_PL 129024
#define A_LR 147456             // float[2][128] final l exchange
#define A_KM 148480             // int[2][64] mask
#define A_TOT 149504

__global__ void __launch_bounds__(256)
attn_mma(const unsigned short* __restrict__ qh, const unsigned short* __restrict__ ql,
         const int* __restrict__ mask,
         unsigned short* __restrict__ outh, unsigned short* __restrict__ outl)
{
    extern __shared__ __align__(16) char asmem[];
    const uint32_t sb = su32(asmem);
    float* lred = (float*)(asmem + A_LR);
    int*   kvm  = (int*)  (asmem + A_KM);

    const int tid = threadIdx.x, lane = tid & 31, wid = tid >> 5;
    const int wm = wid & 3, wn = wid >> 2;
    const int q0 = blockIdx.x * 128;
    const int b  = blockIdx.y >> 3;
    const int h  = blockIdx.y & 7;
    const int RS = 3 * D_;

    // ---- load Q tile [128][64] hi/lo ----
    {
        const int r_ = tid >> 3, sg = tid & 7;
        #pragma unroll
        for (int i = 0; i < 4; i++) {
            int r = r_ + 32*i;
            size_t g = (size_t)(b*S_ + q0 + r)*RS + h*DH + sg*8;
            cp16(sb + A_QH + r*AST + sg*16, qh + g);
            cp16(sb + A_QL + r*AST + sg*16, ql + g);
        }
    }

    // ---- KV tile loader ----
    auto load_kv = [&](int j, int s) {
        const int r_ = tid >> 3, sg = tid & 7;
        #pragma unroll
        for (int i = 0; i < 2; i++) {
            int r = r_ + 32*i;
            size_t gk = (size_t)(b*S_ + j*64 + r)*RS + D_   + h*DH + sg*8;
            size_t gv = (size_t)(b*S_ + j*64 + r)*RS + 2*D_ + h*DH + sg*8;
            uint32_t so = s*9216 + r*AST + sg*16;
            cp16(sb + A_KH + so, qh + gk);
            cp16(sb + A_KL + so, ql + gk);
            cp16(sb + A_VH + so, qh + gv);
            cp16(sb + A_VL + so, ql + gv);
        }
        if (tid < 64) kvm[s*64 + tid] = mask[b*S_ + j*64 + tid];
        asm volatile("cp.async.commit_group;" ::: "memory");
    };
    load_kv(0, 0);

    float oacc[2][4][4];
    #pragma unroll
    for (int i = 0; i < 2; i++)
        #pragma unroll
        for (int j = 0; j < 4; j++)
            #pragma unroll
            for (int k = 0; k < 4; k++) oacc[i][j][k] = 0.f;
    float lreg[2][2] = {{0.f, 0.f}, {0.f, 0.f}};

    const uint32_t lrow = lane & 15;
    const uint32_t lcol = (lane >> 4) * 16;
    const int qr  = lane >> 2;        // row-within-8 for C fragments
    const int cc2 = (lane & 3) * 2;   // col pair base

    for (int j = 0; j < S_/64; j++) {
        const int s = j & 1;
        asm volatile("cp.async.wait_group 0;" ::: "memory");
        __syncthreads();
        if (j + 1 < S_/64) load_kv(j + 1, s ^ 1);

        // ---- S = Q K^T (3-term split) ----
        float sacc[2][4][4];
        #pragma unroll
        for (int i = 0; i < 2; i++)
            #pragma unroll
            for (int jj = 0; jj < 4; jj++)
                #pragma unroll
                for (int k = 0; k < 4; k++) sacc[i][jj][k] = 0.f;

        #pragma unroll
        for (int ks = 0; ks < 4; ks++) {           // dh = 64 -> 4 k16 steps
            const uint32_t kb = ks*32 + lcol;
            uint32_t aH[2][4], aL[2][4], bH[4][2], bL[4][2];
            #pragma unroll
            for (int mt = 0; mt < 2; mt++) {
                uint32_t ad = sb + (wm*32 + mt*16 + lrow)*AST + kb;
                ldsm4(aH[mt], ad + A_QH);
                ldsm4(aL[mt], ad + A_QL);
            }
            #pragma unroll
            for (int g = 0; g < 2; g++) {
                uint32_t bd = sb + s*9216 + (wn*32 + g*16 + lrow)*AST + kb;
                uint32_t t0[4], t1[4];
                ldsm4(t0, bd + A_KH);
                ldsm4(t1, bd + A_KL);
                bH[g*2][0] = t0[0]; bH[g*2][1] = t0[2];
                bH[g*2+1][0] = t0[1]; bH[g*2+1][1] = t0[3];
                bL[g*2][0] = t1[0]; bL[g*2][1] = t1[2];
                bL[g*2+1][0] = t1[1]; bL[g*2+1][1] = t1[3];
            }
            #pragma unroll
            for (int mt = 0; mt < 2; mt++)
                #pragma unroll
                for (int nt = 0; nt < 4; nt++) {
                    mma_bf16(sacc[mt][nt], aH[mt], bH[nt]);
                    mma_bf16(sacc[mt][nt], aH[mt], bL[nt]);
                    mma_bf16(sacc[mt][nt], aL[mt], bH[nt]);
                }
        }

        // ---- direct exp + mask, register l accumulation, P store ----
        #pragma unroll
        for (int nt = 0; nt < 4; nt++) {
            int col = wn*32 + nt*8 + cc2;
            const bool live0 = (kvm[s*64 + col]     != 0);
            const bool live1 = (kvm[s*64 + col + 1] != 0);
            #pragma unroll
            for (int mt = 0; mt < 2; mt++)
                #pragma unroll
                for (int half = 0; half < 2; half++) {
                    float p0 = live0 ? __expf(sacc[mt][nt][2*half])   : 0.f;
                    float p1 = live1 ? __expf(sacc[mt][nt][2*half+1]) : 0.f;
                    lreg[mt][half] += p0 + p1;
                    int row = wm*32 + mt*16 + half*8 + qr;
                    ushort2 hh, ll;
                    bf16_split(p0, hh.x, ll.x);
                    bf16_split(p1, hh.y, ll.y);
                    uint32_t po = row*AST + col*2;
                    *(ushort2*)(asmem + A_PH + po) = hh;
                    *(ushort2*)(asmem + A_PL + po) = ll;
                }
        }
        __syncthreads();

        // ---- O += P V (3-term split) ----
        #pragma unroll
        for (int ks = 0; ks < 4; ks++) {           // 64 keys -> 4 k16 steps
            const uint32_t kb = ks*32 + lcol;
            uint32_t pHf[2][4], pLf[2][4], vHf[4][2], vLf[4][2];
            #pragma unroll
            for (int mt = 0; mt < 2; mt++) {
                uint32_t ad = sb + (wm*32 + mt*16 + lrow)*AST + kb;
                ldsm4(pHf[mt], ad + A_PH);
                ldsm4(pLf[mt], ad + A_PL);
            }
            #pragma unroll
            for (int g = 0; g < 2; g++) {
                uint32_t va = sb + s*9216
                            + (ks*16 + (lane & 7) + 8*((lane >> 3) & 1))*AST
                            + (wn*32 + g*16 + 8*(lane >> 4))*2;
                uint32_t t0[4], t1[4];
                ldsm4t(t0, va + A_VH);
                ldsm4t(t1, va + A_VL);
                vHf[g*2][0] = t0[0]; vHf[g*2][1] = t0[1];
                vHf[g*2+1][0] = t0[2]; vHf[g*2+1][1] = t0[3];
                vLf[g*2][0] = t1[0]; vLf[g*2][1] = t1[1];
                vLf[g*2+1][0] = t1[2]; vLf[g*2+1][1] = t1[3];
            }
            #pragma unroll
            for (int mt = 0; mt < 2; mt++)
                #pragma unroll
                for (int nt = 0; nt < 4; nt++) {
                    mma_bf16(oacc[mt][nt], pHf[mt], vHf[nt]);
                    mma_bf16(oacc[mt][nt], pHf[mt], vLf[nt]);
                    mma_bf16(oacc[mt][nt], pLf[mt], vHf[nt]);
                }
        }
    }

    // ---- final l reduction: over lane group (cols of this warp), then over wn ----
    #pragma unroll
    for (int mt = 0; mt < 2; mt++)
        #pragma unroll
        for (int half = 0; half < 2; half++) {
            float v = lreg[mt][half];
            v += __shfl_xor_sync(0xffffffffu, v, 1);
            v += __shfl_xor_sync(0xffffffffu, v, 2);
            lreg[mt][half] = v;
        }
    __syncthreads();   // P buffer reads done; lred region free
    if ((lane & 3) == 0) {
        #pragma unroll
        for (int mt = 0; mt < 2; mt++)
            #pragma unroll
            for (int half = 0; half < 2; half++) {
                int row = wm*32 + mt*16 + half*8 + qr;
                lred[wn*128 + row] = lreg[mt][half];
            }
    }
    __syncthreads();

    // ---- finalize: divide by l, write bf16 hi/lo ----
    #pragma unroll
    for (int mt = 0; mt < 2; mt++)
        #pragma unroll
        for (int half = 0; half < 2; half++) {
            int row = wm*32 + mt*16 + half*8 + qr;
            float linv = 1.f / (lred[row] + lred[128 + row]);
            size_t base = (size_t)(b*S_ + q0 + row)*D_ + h*DH;
            #pragma unroll
            for (int nt = 0; nt < 4; nt++) {
                int d = wn*32 + nt*8 + cc2;
                float w0 = oacc[mt][nt][2*half]   * linv;
                float w1 = oacc[mt][nt][2*half+1] * linv;
                ushort2 hh, ll;
                bf16_split(w0, hh.x, ll.x);
                bf16_split(w1, hh.y, ll.y);
                *(ushort2*)&outh[base + d] = hh;
                *(ushort2*)&outl[base + d] = ll;
            }
        }
}

// ============================================================================
// LayerNorm over last dim (512); optional bf16 hi/lo side outputs
// ============================================================================
template<bool SPLIT>
__global__ void __launch_bounds__(256)
ln_kernel(const float* __restrict__ X, const float* __restrict__ g,
          const float* __restrict__ bta, float* __restrict__ Y,
          unsigned short* __restrict__ Yh, unsigned short* __restrict__ Yl)
{
    __shared__ float red[32];
    const int row = blockIdx.x;
    const int t = threadIdx.x;
    const int lane = t & 31, w = t >> 5;

    float2 v = ((const float2*)(X + (size_t)row*D_))[t];

    float s = v.x + v.y;
    #pragma unroll
    for (int o = 16; o; o >>= 1) s += __shfl_xor_sync(0xffffffffu, s, o);
    if (lane == 0) red[w] = s;
    __syncthreads();
    if (t < 32) {
        float a = (t < 8) ? red[t] : 0.f;
        #pragma unroll
        for (int o = 4; o; o >>= 1) a += __shfl_xor_sync(0xffffffffu, a, o);
        if (t == 0) red[0] = a;
    }
    __syncthreads();
    const float mu = red[0] * (1.f / D_);
    __syncthreads();

    float d0 = v.x - mu, d1 = v.y - mu;
    float q = d0*d0 + d1*d1;
    #pragma unroll
    for (int o = 16; o; o >>= 1) q += __shfl_xor_sync(0xffffffffu, q, o);
    if (lane == 0) red[w] = q;
    __syncthreads();
    if (t < 32) {
        float a = (t < 8) ? red[t] : 0.f;
        #pragma unroll
        for (int o = 4; o; o >>= 1) a += __shfl_xor_sync(0xffffffffu, a, o);
        if (t == 0) red[0] = a;
    }
    __syncthreads();
    const float var = red[0] * (1.f / D_);
    const float inv = rsqrtf(var + 1e-5f);

    float2 gv = ((const float2*)g)[t];
    float2 bv = ((const float2*)bta)[t];
    float y0 = d0 * inv * gv.x + bv.x;
    float y1 = d1 * inv * gv.y + bv.y;
    float2 o2; o2.x = y0; o2.y = y1;
    ((float2*)(Y + (size_t)row*D_))[t] = o2;
    if (SPLIT) {
        ushort2 hh, ll;
        bf16_split(y0, hh.x, ll.x);
        bf16_split(y1, hh.y, ll.y);
        ((ushort2*)(Yh + (size_t)row*D_))[t] = hh;
        ((ushort2*)(Yl + (size_t)row*D_))[t] = ll;
    }
}

// ============================================================================
// Host launcher
// ============================================================================
extern "C" void kernel_launch(void* const* d_in, const int* in_sizes, int n_in,
                              void* d_out, int out_size)
{
    const float* x_in  = (const float*)d_in[0];
    const int*   mask  = (const int*)d_in[3];
    const float* Wqkv  = (const float*)d_in[4];
    const float* Wfc   = (const float*)d_in[5];
    const float* bfc   = (const float*)d_in[6];
    const float* ln1g  = (const float*)d_in[7];
    const float* ln1b  = (const float*)d_in[8];
    const float* ln2g  = (const float*)d_in[9];
    const float* ln2b  = (const float*)d_in[10];
    const float* W1    = (const float*)d_in[11];
    const float* b1    = (const float*)d_in[12];
    const float* W2    = (const float*)d_in[13];
    const float* b2    = (const float*)d_in[14];
    float* out = (float*)d_out;

    float *px, *pt;
    unsigned short *pqh, *pql, *pxh, *pxl, *pah, *pal, *phh, *phl, *pwh, *pwl;
    cudaGetSymbolAddress((void**)&px,   g_x);
    cudaGetSymbolAddress((void**)&pt,   g_t);
    cudaGetSymbolAddress((void**)&pqh,  g_qh);
    cudaGetSymbolAddress((void**)&pql,  g_ql);
    cudaGetSymbolAddress((void**)&pxh,  g_xh);
    cudaGetSymbolAddress((void**)&pxl,  g_xl);
    cudaGetSymbolAddress((void**)&pah,  g_ah);
    cudaGetSymbolAddress((void**)&pal,  g_al);
    cudaGetSymbolAddress((void**)&phh,  g_hh);
    cudaGetSymbolAddress((void**)&phl,  g_hl);
    cudaGetSymbolAddress((void**)&pwh,  g_wth);
    cudaGetSymbolAddress((void**)&pwl,  g_wtl);

    const int GSM = NSTG * STG_B;   // 120 KB
    cudaFuncSetAttribute(gemm_mma<1>, cudaFuncAttributeMaxDynamicSharedMemorySize, GSM);
    cudaFuncSetAttribute(gemm_mma<2>, cudaFuncAttributeMaxDynamicSharedMemorySize, GSM);
    cudaFuncSetAttribute(gemm_mma<3>, cudaFuncAttributeMaxDynamicSharedMemorySize, GSM);
    cudaFuncSetAttribute(attn_mma, cudaFuncAttributeMaxDynamicSharedMemorySize, A_TOT);

    // weight transpose + bf16 split (all layers)
    transpose_split_kernel<<<dim3(1536/32, 512/32, L_), dim3(32,8)>>>(Wqkv, pwh, pwl, 512, 1536, OFF_QKV);
    transpose_split_kernel<<<dim3( 512/32, 512/32, L_), dim3(32,8)>>>(Wfc,  pwh, pwl, 512,  512, OFF_FC);
    transpose_split_kernel<<<dim3(2048/32, 512/32, L_), dim3(32,8)>>>(W1,   pwh, pwl, 512, 2048, OFF_W1);
    transpose_split_kernel<<<dim3( 512/32,2048/32, L_), dim3(32,8)>>>(W2,   pwh, pwl, 2048, 512, OFF_W2);

    // position embedding
    pos_scan_kernel<<<B_, S_>>>(mask);
    add_pos_kernel<<<(M_*D_)/256, 256>>>(x_in);

    for (int l = 0; l < L_; l++) {
        const unsigned short* wqh = pwh + (size_t)l*WT_L + OFF_QKV;
        const unsigned short* wql = pwl + (size_t)l*WT_L + OFF_QKV;
        const unsigned short* wfh = pwh + (size_t)l*WT_L + OFF_FC;
        const unsigned short* wfl = pwl + (size_t)l*WT_L + OFF_FC;
        const unsigned short* w1h = pwh + (size_t)l*WT_L + OFF_W1;
        const unsigned short* w1l = pwl + (size_t)l*WT_L + OFF_W1;
        const unsigned short* w2h = pwh + (size_t)l*WT_L + OFF_W2;
        const unsigned short* w2l = pwl + (size_t)l*WT_L + OFF_W2;

        // qkv = x @ Wqkv  [8192,512]x[512,1536] -> bf16 hi/lo
        gemm_mma<3><<<dim3(12, 64), 256, GSM>>>(pxh, pxl, wqh, wql,
            nullptr, nullptr, nullptr, pqh, pql, 3*D_, D_);

        // attention (tensor-core flash, direct-exp) -> att bf16 hi/lo
        attn_mma<<<dim3(S_/128, B_*H_), 256, A_TOT>>>(pqh, pql, mask, pah, pal);

        // o @ Wfc + bfc + residual(x) -> t ; LN1 -> x (+hi/lo)
        gemm_mma<1><<<dim3(4, 64), 256, GSM>>>(pah, pal, wfh, wfl,
            bfc + (size_t)l*D_, px, pt, nullptr, nullptr, D_, D_);
        ln_kernel<true><<<M_, 256>>>(pt, ln1g + (size_t)l*D_, ln1b + (size_t)l*D_,
                                     px, pxh, pxl);

        // h = relu(x @ W1 + b1) -> bf16 hi/lo
        gemm_mma<2><<<dim3(16, 64), 256, GSM>>>(pxh, pxl, w1h, w1l,
            b1 + (size_t)l*FF_, nullptr, nullptr, phh, phl, FF_, D_);

        // h @ W2 + b2 + residual(x) -> t ; LN2 -> x (+hi/lo) or d_out
        gemm_mma<1><<<dim3(4, 64), 256, GSM>>>(phh, phl, w2h, w2l,
            b2 + (size_t)l*D_, px, pt, nullptr, nullptr, D_, FF_);
        if (l == L_-1)
            ln_kernel<false><<<M_, 256>>>(pt, ln2g + (size_t)l*D_, ln2b + (size_t)l*D_,
                                          out, nullptr, nullptr);
        else
            ln_kernel<true><<<M_, 256>>>(pt, ln2g + (size_t)l*D_, ln2b + (size_t)l*D_,
                                         px, pxh, pxl);
    }
}

// round 10
// speedup vs baseline: 1.0918x; 1.0918x over previous
#include <cuda_runtime.h>
#include <cuda_bf16.h>
#include <math.h>
#include <stdint.h>

// Problem constants
#define B_  8
#define S_  1024
#define D_  512
#define H_  8
#define DH  64
#define FF_ 2048
#define L_  6
#define M_  (B_*S_)   // 8192 rows

// Transposed-weight layout (bf16 hi/lo), per layer:
#define OFF_QKV 0
#define OFF_FC  786432
#define OFF_W1  1048576
#define OFF_W2  2097152
#define WT_L    3145728
#define WT_TOT  (WT_L*L_)

// ---------------- scratch (static device globals; no allocation) ----------------
__device__ float g_x[M_*D_];                 // fp32 activations (residual stream)
__device__ float g_t[M_*D_];                 // pre-LN temp
__device__ unsigned short g_qh[M_*3*D_], g_ql[M_*3*D_]; // qkv bf16 hi/lo
__device__ unsigned short g_xh[M_*D_],  g_xl[M_*D_];    // x bf16 hi/lo
__device__ unsigned short g_ah[M_*D_],  g_al[M_*D_];    // attention out bf16 hi/lo
__device__ unsigned short g_hh[M_*FF_], g_hl[M_*FF_];   // ffn hidden bf16 hi/lo
__device__ unsigned short g_wth[WT_TOT], g_wtl[WT_TOT]; // transposed weights bf16 hi/lo
__device__ int g_pos[M_];

// ============================================================================
// helpers (baseline sm_80+ PTX only — no tcgen05 on this toolchain target)
// ============================================================================
__device__ __forceinline__ uint32_t su32(const void* p) {
    uint32_t a;
    asm("{ .reg .u64 t; cvta.to.shared.u64 t, %1; cvt.u32.u64 %0, t; }"
        : "=r"(a) : "l"(p));
    return a;
}

__device__ __forceinline__ void cp16(uint32_t s, const void* g) {
    asm volatile("cp.async.cg.shared.global [%0], [%1], 16;" :: "r"(s), "l"(g) : "memory");
}

__device__ __forceinline__ void ldsm4(uint32_t* r, uint32_t addr) {
    asm volatile("ldmatrix.sync.aligned.m8n8.x4.shared.b16 {%0,%1,%2,%3}, [%4];"
        : "=r"(r[0]), "=r"(r[1]), "=r"(r[2]), "=r"(r[3]) : "r"(addr));
}

__device__ __forceinline__ void ldsm4t(uint32_t* r, uint32_t addr) {
    asm volatile("ldmatrix.sync.aligned.m8n8.x4.trans.shared.b16 {%0,%1,%2,%3}, [%4];"
        : "=r"(r[0]), "=r"(r[1]), "=r"(r[2]), "=r"(r[3]) : "r"(addr));
}

__device__ __forceinline__ void mma_bf16(float* c, const uint32_t* a, const uint32_t* b) {
    asm volatile(
        "mma.sync.aligned.m16n8k16.row.col.f32.bf16.bf16.f32 "
        "{%0,%1,%2,%3}, {%4,%5,%6,%7}, {%8,%9}, {%0,%1,%2,%3};"
        : "+f"(c[0]), "+f"(c[1]), "+f"(c[2]), "+f"(c[3])
        : "r"(a[0]), "r"(a[1]), "r"(a[2]), "r"(a[3]), "r"(b[0]), "r"(b[1]));
}

__device__ __forceinline__ void bf16_split(float v, unsigned short& hi, unsigned short& lo) {
    __nv_bfloat16 h = __float2bfloat16(v);
    hi = __bfloat16_as_ushort(h);
    lo = __bfloat16_as_ushort(__float2bfloat16(v - __bfloat162float(h)));
}

// ============================================================================
// Position scan
// ============================================================================
__global__ void pos_scan_kernel(const int* __restrict__ mask)
{
    __shared__ int sc[S_];
    int b = blockIdx.x;
    int t = threadIdx.x;
    int v = (mask[b*S_ + t] != 0) ? 1 : 0;
    sc[t] = v;
    __syncthreads();
    for (int off = 1; off < S_; off <<= 1) {
        int add = (t >= off) ? sc[t - off] : 0;
        __syncthreads();
        sc[t] += add;
        __syncthreads();
    }
    g_pos[b*S_ + t] = v ? sc[t] : 0;
}

// ============================================================================
// x = x_in + sin_table[pos]; emit fp32 + bf16 hi/lo
// ============================================================================
__global__ void add_pos_kernel(const float* __restrict__ xin)
{
    int idx = blockIdx.x * 256 + threadIdx.x;
    int d = idx & (D_-1);
    int row = idx >> 9;
    int pos = g_pos[row];
    float e = 0.f;
    if (pos > 0) {
        const float c = -9.210340371976184f / 255.0f;
        if (d < 256) e = sinf((float)pos * expf((float)d * c));
        else         e = cosf((float)pos * expf((float)(d - 256) * c));
    }
    float v = xin[idx] + e;
    g_x[idx] = v;
    bf16_split(v, g_xh[idx], g_xl[idx]);
}

// ============================================================================
// Weight transpose + bf16 split: W[K,N] -> T_hi/T_lo [N,K]  (grid.z = layer)
// ============================================================================
__global__ void transpose_split_kernel(const float* __restrict__ W,
                                       unsigned short* __restrict__ Th,
                                       unsigned short* __restrict__ Tl,
                                       int K, int N, size_t out_off)
{
    __shared__ float t[32][33];
    int l = blockIdx.z;
    const float* Wp = W + (size_t)l * K * N;
    unsigned short* Thp = Th + (size_t)l * WT_L + out_off;
    unsigned short* Tlp = Tl + (size_t)l * WT_L + out_off;
    int n0 = blockIdx.x * 32, k0 = blockIdx.y * 32;
    int tx = threadIdx.x, ty = threadIdx.y;   // 32 x 8
    #pragma unroll
    for (int i = 0; i < 4; i++)
        t[ty + 8*i][tx] = Wp[(size_t)(k0 + ty + 8*i) * N + n0 + tx];
    __syncthreads();
    #pragma unroll
    for (int i = 0; i < 4; i++) {
        float v = t[tx][ty + 8*i];
        size_t o = (size_t)(n0 + ty + 8*i) * K + k0 + tx;
        bf16_split(v, Thp[o], Tlp[o]);
    }
}

// ============================================================================
// mma.sync bf16 GEMM: C[M,N] = A[M,K] @ B^T (B given as [N,K] bf16 hi/lo rows)
// 3-term split AhBh + AhBl + AlBh, fp32 accum.
// CTA 128x128, BK=32, 256 thr, 8 warps (2x4) of 64x32, cp.async double buffer.
// (Round-7 proven structure: 2 stages / 80KB / two syncs per chunk.)
// EPI: 0 = fp32 out; 1 = +bias +Res fp32 out; 2 = relu(+bias) -> bf16 hi/lo;
//      3 = plain -> bf16 hi/lo
// ============================================================================
#define BK 32
#define ROW_B 80            // smem row stride bytes (40 bf16, conflict-free)
#define TEN_B 10240         // 128 rows * 80B
#define STG_B (4*TEN_B)     // 4 tensors per stage

template<int EPI>
__global__ void __launch_bounds__(256)
gemm_mma(const unsigned short* __restrict__ Ah, const unsigned short* __restrict__ Al,
         const unsigned short* __restrict__ Bh, const unsigned short* __restrict__ Bl,
         const float* __restrict__ bias, const float* __restrict__ Res,
         float* __restrict__ Cf,
         unsigned short* __restrict__ Ch, unsigned short* __restrict__ Cl,
         int N, int K)
{
    extern __shared__ __align__(16) char smem[];
    const uint32_t sb = su32(smem);
    const int tid = threadIdx.x;
    const int lane = tid & 31, wid = tid >> 5;
    const int wm = wid & 1, wn = wid >> 1;
    const int m0 = blockIdx.y * 128, n0 = blockIdx.x * 128;

    float acc[4][4][4];
    #pragma unroll
    for (int i = 0; i < 4; i++)
        #pragma unroll
        for (int j = 0; j < 4; j++)
            #pragma unroll
            for (int k = 0; k < 4; k++) acc[i][j][k] = 0.f;

    const int nc = K / BK;

    auto load_chunk = [&](int c, int stage) {
        const uint32_t st = sb + stage * STG_B;
        const int k0 = c * BK;
        #pragma unroll
        for (int j = 0; j < 2; j++) {
            int idx = tid * 2 + j;          // 0..511
            int r = idx >> 2, sg = idx & 3;
            uint32_t so = r * ROW_B + sg * 16;
            const size_t ga = (size_t)(m0 + r) * K + k0 + sg * 8;
            const size_t gb = (size_t)(n0 + r) * K + k0 + sg * 8;
            cp16(st +           so, Ah + ga);
            cp16(st +   TEN_B + so, Al + ga);
            cp16(st + 2*TEN_B + so, Bh + gb);
            cp16(st + 3*TEN_B + so, Bl + gb);
        }
        asm volatile("cp.async.commit_group;" ::: "memory");
    };

    auto compute_chunk = [&](int stage) {
        const uint32_t st = sb + stage * STG_B;
        const uint32_t lrow = (lane & 15);
        const uint32_t lcol = (lane >> 4) * 16;
        #pragma unroll
        for (int ks = 0; ks < 2; ks++) {
            const uint32_t kb = ks * 32 + lcol;
            uint32_t aH[4][4], aL[4][4], bH[4][2], bL[4][2];
            #pragma unroll
            for (int mt = 0; mt < 4; mt++) {
                uint32_t ad = st + (wm*64 + mt*16 + lrow) * ROW_B + kb;
                ldsm4(aH[mt], ad);
                ldsm4(aL[mt], ad + TEN_B);
            }
            #pragma unroll
            for (int g = 0; g < 2; g++) {
                uint32_t bd = st + 2*TEN_B + (wn*32 + g*16 + lrow) * ROW_B + kb;
                uint32_t t0[4], t1[4];
                ldsm4(t0, bd);
                ldsm4(t1, bd + TEN_B);
                bH[g*2][0] = t0[0]; bH[g*2][1] = t0[2];
                bH[g*2+1][0] = t0[1]; bH[g*2+1][1] = t0[3];
                bL[g*2][0] = t1[0]; bL[g*2][1] = t1[2];
                bL[g*2+1][0] = t1[1]; bL[g*2+1][1] = t1[3];
            }
            #pragma unroll
            for (int mt = 0; mt < 4; mt++)
                #pragma unroll
                for (int nt = 0; nt < 4; nt++) {
                    mma_bf16(acc[mt][nt], aH[mt], bH[nt]);
                    mma_bf16(acc[mt][nt], aH[mt], bL[nt]);
                    mma_bf16(acc[mt][nt], aL[mt], bH[nt]);
                }
        }
    };

    load_chunk(0, 0);
    for (int c = 0; c < nc; c++) {
        if (c + 1 < nc) {
            load_chunk(c + 1, (c + 1) & 1);
            asm volatile("cp.async.wait_group 1;" ::: "memory");
        } else {
            asm volatile("cp.async.wait_group 0;" ::: "memory");
        }
        __syncthreads();
        compute_chunk(c & 1);
        __syncthreads();
    }

    // ---- epilogue ----
    const int r0 = lane >> 2;
    const int cp = (lane & 3) * 2;
    #pragma unroll
    for (int mt = 0; mt < 4; mt++) {
        #pragma unroll
        for (int half = 0; half < 2; half++) {
            const size_t row = (size_t)(m0 + wm*64 + mt*16 + half*8 + r0);
            #pragma unroll
            for (int nt = 0; nt < 4; nt++) {
                const int col = n0 + wn*32 + nt*8 + cp;
                float v0 = acc[mt][nt][half*2 + 0];
                float v1 = acc[mt][nt][half*2 + 1];
                if (EPI == 0) {
                    float2 o; o.x = v0; o.y = v1;
                    *(float2*)&Cf[row*N + col] = o;
                } else if (EPI == 1) {
                    float2 bb = *(const float2*)&bias[col];
                    float2 rr = *(const float2*)&Res[row*N + col];
                    float2 o; o.x = v0 + bb.x + rr.x; o.y = v1 + bb.y + rr.y;
                    *(float2*)&Cf[row*N + col] = o;
                } else {
                    if (EPI == 2) {
                        float2 bb = *(const float2*)&bias[col];
                        v0 = fmaxf(v0 + bb.x, 0.f);
                        v1 = fmaxf(v1 + bb.y, 0.f);
                    }
                    ushort2 hh, ll;
                    bf16_split(v0, hh.x, ll.x);
                    bf16_split(v1, hh.y, ll.y);
                    *(ushort2*)&Ch[row*N + col] = hh;
                    *(ushort2*)&Cl[row*N + col] = ll;
                }
            }
        }
    }
}

// ============================================================================
// Flash attention via mma.sync bf16 (hi/lo split, 3-term): scale = 1.
// DIRECT-EXP softmax: p = exp(s) in fp32 (no running max; |s| is O(10) here),
// row-sum l accumulated in registers, single normalization at the end.
// CTA: 128 q-rows x full S keys (64-key tiles). 256 thr, warps 4(m) x 2(n).
// ============================================================================
#define AST 144                 // smem row stride bytes (64 bf16 + 16B pad)
#define A_QH 0
#define A_QL 18432
#define A_KH 36864              // + stage*9216
#define A_KL 55296
#define A_VH 73728
#define A_VL 92160
#define A_PH 110592             // single-buffered (sync-protected)
#define A_PL 129024
#define A_LR 147456             // float[2][128] final l exchange
#define A_KM 148480             // int[2][64] mask
#define A_TOT 149504

__global__ void __launch_bounds__(256)
attn_mma(const unsigned short* __restrict__ qh, const unsigned short* __restrict__ ql,
         const int* __restrict__ mask,
         unsigned short* __restrict__ outh, unsigned short* __restrict__ outl)
{
    extern __shared__ __align__(16) char asmem[];
    const uint32_t sb = su32(asmem);
    float* lred = (float*)(asmem + A_LR);
    int*   kvm  = (int*)  (asmem + A_KM);

    const int tid = threadIdx.x, lane = tid & 31, wid = tid >> 5;
    const int wm = wid & 3, wn = wid >> 2;
    const int q0 = blockIdx.x * 128;
    const int b  = blockIdx.y >> 3;
    const int h  = blockIdx.y & 7;
    const int RS = 3 * D_;

    // ---- load Q tile [128][64] hi/lo ----
    {
        const int r_ = tid >> 3, sg = tid & 7;
        #pragma unroll
        for (int i = 0; i < 4; i++) {
            int r = r_ + 32*i;
            size_t g = (size_t)(b*S_ + q0 + r)*RS + h*DH + sg*8;
            cp16(sb + A_QH + r*AST + sg*16, qh + g);
            cp16(sb + A_QL + r*AST + sg*16, ql + g);
        }
    }

    // ---- KV tile loader ----
    auto load_kv = [&](int j, int s) {
        const int r_ = tid >> 3, sg = tid & 7;
        #pragma unroll
        for (int i = 0; i < 2; i++) {
            int r = r_ + 32*i;
            size_t gk = (size_t)(b*S_ + j*64 + r)*RS + D_   + h*DH + sg*8;
            size_t gv = (size_t)(b*S_ + j*64 + r)*RS + 2*D_ + h*DH + sg*8;
            uint32_t so = s*9216 + r*AST + sg*16;
            cp16(sb + A_KH + so, qh + gk);
            cp16(sb + A_KL + so, ql + gk);
            cp16(sb + A_VH + so, qh + gv);
            cp16(sb + A_VL + so, ql + gv);
        }
        if (tid < 64) kvm[s*64 + tid] = mask[b*S_ + j*64 + tid];
        asm volatile("cp.async.commit_group;" ::: "memory");
    };
    load_kv(0, 0);

    float oacc[2][4][4];
    #pragma unroll
    for (int i = 0; i < 2; i++)
        #pragma unroll
        for (int j = 0; j < 4; j++)
            #pragma unroll
            for (int k = 0; k < 4; k++) oacc[i][j][k] = 0.f;
    float lreg[2][2] = {{0.f, 0.f}, {0.f, 0.f}};

    const uint32_t lrow = lane & 15;
    const uint32_t lcol = (lane >> 4) * 16;
    const int qr  = lane >> 2;        // row-within-8 for C fragments
    const int cc2 = (lane & 3) * 2;   // col pair base

    for (int j = 0; j < S_/64; j++) {
        const int s = j & 1;
        asm volatile("cp.async.wait_group 0;" ::: "memory");
        __syncthreads();
        if (j + 1 < S_/64) load_kv(j + 1, s ^ 1);

        // ---- S = Q K^T (3-term split) ----
        float sacc[2][4][4];
        #pragma unroll
        for (int i = 0; i < 2; i++)
            #pragma unroll
            for (int jj = 0; jj < 4; jj++)
                #pragma unroll
                for (int k = 0; k < 4; k++) sacc[i][jj][k] = 0.f;

        #pragma unroll
        for (int ks = 0; ks < 4; ks++) {           // dh = 64 -> 4 k16 steps
            const uint32_t kb = ks*32 + lcol;
            uint32_t aH[2][4], aL[2][4], bH[4][2], bL[4][2];
            #pragma unroll
            for (int mt = 0; mt < 2; mt++) {
                uint32_t ad = sb + (wm*32 + mt*16 + lrow)*AST + kb;
                ldsm4(aH[mt], ad + A_QH);
                ldsm4(aL[mt], ad + A_QL);
            }
            #pragma unroll
            for (int g = 0; g < 2; g++) {
                uint32_t bd = sb + s*9216 + (wn*32 + g*16 + lrow)*AST + kb;
                uint32_t t0[4], t1[4];
                ldsm4(t0, bd + A_KH);
                ldsm4(t1, bd + A_KL);
                bH[g*2][0] = t0[0]; bH[g*2][1] = t0[2];
                bH[g*2+1][0] = t0[1]; bH[g*2+1][1] = t0[3];
                bL[g*2][0] = t1[0]; bL[g*2][1] = t1[2];
                bL[g*2+1][0] = t1[1]; bL[g*2+1][1] = t1[3];
            }
            #pragma unroll
            for (int mt = 0; mt < 2; mt++)
                #pragma unroll
                for (int nt = 0; nt < 4; nt++) {
                    mma_bf16(sacc[mt][nt], aH[mt], bH[nt]);
                    mma_bf16(sacc[mt][nt], aH[mt], bL[nt]);
                    mma_bf16(sacc[mt][nt], aL[mt], bH[nt]);
                }
        }

        // ---- direct exp + mask, register l accumulation, P store ----
        #pragma unroll
        for (int nt = 0; nt < 4; nt++) {
            int col = wn*32 + nt*8 + cc2;
            const bool live0 = (kvm[s*64 + col]     != 0);
            const bool live1 = (kvm[s*64 + col + 1] != 0);
            #pragma unroll
            for (int mt = 0; mt < 2; mt++)
                #pragma unroll
                for (int half = 0; half < 2; half++) {
                    float p0 = live0 ? __expf(sacc[mt][nt][2*half])   : 0.f;
                    float p1 = live1 ? __expf(sacc[mt][nt][2*half+1]) : 0.f;
                    lreg[mt][half] += p0 + p1;
                    int row = wm*32 + mt*16 + half*8 + qr;
                    ushort2 hh, ll;
                    bf16_split(p0, hh.x, ll.x);
                    bf16_split(p1, hh.y, ll.y);
                    uint32_t po = row*AST + col*2;
                    *(ushort2*)(asmem + A_PH + po) = hh;
                    *(ushort2*)(asmem + A_PL + po) = ll;
                }
        }
        __syncthreads();

        // ---- O += P V (3-term split) ----
        #pragma unroll
        for (int ks = 0; ks < 4; ks++) {           // 64 keys -> 4 k16 steps
            const uint32_t kb = ks*32 + lcol;
            uint32_t pHf[2][4], pLf[2][4], vHf[4][2], vLf[4][2];
            #pragma unroll
            for (int mt = 0; mt < 2; mt++) {
                uint32_t ad = sb + (wm*32 + mt*16 + lrow)*AST + kb;
                ldsm4(pHf[mt], ad + A_PH);
                ldsm4(pLf[mt], ad + A_PL);
            }
            #pragma unroll
            for (int g = 0; g < 2; g++) {
                uint32_t va = sb + s*9216
                            + (ks*16 + (lane & 7) + 8*((lane >> 3) & 1))*AST
                            + (wn*32 + g*16 + 8*(lane >> 4))*2;
                uint32_t t0[4], t1[4];
                ldsm4t(t0, va + A_VH);
                ldsm4t(t1, va + A_VL);
                vHf[g*2][0] = t0[0]; vHf[g*2][1] = t0[1];
                vHf[g*2+1][0] = t0[2]; vHf[g*2+1][1] = t0[3];
                vLf[g*2][0] = t1[0]; vLf[g*2][1] = t1[1];
                vLf[g*2+1][0] = t1[2]; vLf[g*2+1][1] = t1[3];
            }
            #pragma unroll
            for (int mt = 0; mt < 2; mt++)
                #pragma unroll
                for (int nt = 0; nt < 4; nt++) {
                    mma_bf16(oacc[mt][nt], pHf[mt], vHf[nt]);
                    mma_bf16(oacc[mt][nt], pHf[mt], vLf[nt]);
                    mma_bf16(oacc[mt][nt], pLf[mt], vHf[nt]);
                }
        }
    }

    // ---- final l reduction: over lane group (cols of this warp), then over wn ----
    #pragma unroll
    for (int mt = 0; mt < 2; mt++)
        #pragma unroll
        for (int half = 0; half < 2; half++) {
            float v = lreg[mt][half];
            v += __shfl_xor_sync(0xffffffffu, v, 1);
            v += __shfl_xor_sync(0xffffffffu, v, 2);
            lreg[mt][half] = v;
        }
    __syncthreads();   // P buffer reads done; lred region free
    if ((lane & 3) == 0) {
        #pragma unroll
        for (int mt = 0; mt < 2; mt++)
            #pragma unroll
            for (int half = 0; half < 2; half++) {
                int row = wm*32 + mt*16 + half*8 + qr;
                lred[wn*128 + row] = lreg[mt][half];
            }
    }
    __syncthreads();

    // ---- finalize: divide by l, write bf16 hi/lo ----
    #pragma unroll
    for (int mt = 0; mt < 2; mt++)
        #pragma unroll
        for (int half = 0; half < 2; half++) {
            int row = wm*32 + mt*16 + half*8 + qr;
            float linv = 1.f / (lred[row] + lred[128 + row]);
            size_t base = (size_t)(b*S_ + q0 + row)*D_ + h*DH;
            #pragma unroll
            for (int nt = 0; nt < 4; nt++) {
                int d = wn*32 + nt*8 + cc2;
                float w0 = oacc[mt][nt][2*half]   * linv;
                float w1 = oacc[mt][nt][2*half+1] * linv;
                ushort2 hh, ll;
                bf16_split(w0, hh.x, ll.x);
                bf16_split(w1, hh.y, ll.y);
                *(ushort2*)&outh[base + d] = hh;
                *(ushort2*)&outl[base + d] = ll;
            }
        }
}

// ============================================================================
// LayerNorm over last dim (512); optional bf16 hi/lo side outputs
// ============================================================================
template<bool SPLIT>
__global__ void __launch_bounds__(256)
ln_kernel(const float* __restrict__ X, const float* __restrict__ g,
          const float* __restrict__ bta, float* __restrict__ Y,
          unsigned short* __restrict__ Yh, unsigned short* __restrict__ Yl)
{
    __shared__ float red[32];
    const int row = blockIdx.x;
    const int t = threadIdx.x;
    const int lane = t & 31, w = t >> 5;

    float2 v = ((const float2*)(X + (size_t)row*D_))[t];

    float s = v.x + v.y;
    #pragma unroll
    for (int o = 16; o; o >>= 1) s += __shfl_xor_sync(0xffffffffu, s, o);
    if (lane == 0) red[w] = s;
    __syncthreads();
    if (t < 32) {
        float a = (t < 8) ? red[t] : 0.f;
        #pragma unroll
        for (int o = 4; o; o >>= 1) a += __shfl_xor_sync(0xffffffffu, a, o);
        if (t == 0) red[0] = a;
    }
    __syncthreads();
    const float mu = red[0] * (1.f / D_);
    __syncthreads();

    float d0 = v.x - mu, d1 = v.y - mu;
    float q = d0*d0 + d1*d1;
    #pragma unroll
    for (int o = 16; o; o >>= 1) q += __shfl_xor_sync(0xffffffffu, q, o);
    if (lane == 0) red[w] = q;
    __syncthreads();
    if (t < 32) {
        float a = (t < 8) ? red[t] : 0.f;
        #pragma unroll
        for (int o = 4; o; o >>= 1) a += __shfl_xor_sync(0xffffffffu, a, o);
        if (t == 0) red[0] = a;
    }
    __syncthreads();
    const float var = red[0] * (1.f / D_);
    const float inv = rsqrtf(var + 1e-5f);

    float2 gv = ((const float2*)g)[t];
    float2 bv = ((const float2*)bta)[t];
    float y0 = d0 * inv * gv.x + bv.x;
    float y1 = d1 * inv * gv.y + bv.y;
    float2 o2; o2.x = y0; o2.y = y1;
    ((float2*)(Y + (size_t)row*D_))[t] = o2;
    if (SPLIT) {
        ushort2 hh, ll;
        bf16_split(y0, hh.x, ll.x);
        bf16_split(y1, hh.y, ll.y);
        ((ushort2*)(Yh + (size_t)row*D_))[t] = hh;
        ((ushort2*)(Yl + (size_t)row*D_))[t] = ll;
    }
}

// ============================================================================
// Host launcher
// ============================================================================
extern "C" void kernel_launch(void* const* d_in, const int* in_sizes, int n_in,
                              void* d_out, int out_size)
{
    const float* x_in  = (const float*)d_in[0];
    const int*   mask  = (const int*)d_in[3];
    const float* Wqkv  = (const float*)d_in[4];
    const float* Wfc   = (const float*)d_in[5];
    const float* bfc   = (const float*)d_in[6];
    const float* ln1g  = (const float*)d_in[7];
    const float* ln1b  = (const float*)d_in[8];
    const float* ln2g  = (const float*)d_in[9];
    const float* ln2b  = (const float*)d_in[10];
    const float* W1    = (const float*)d_in[11];
    const float* b1    = (const float*)d_in[12];
    const float* W2    = (const float*)d_in[13];
    const float* b2    = (const float*)d_in[14];
    float* out = (float*)d_out;

    float *px, *pt;
    unsigned short *pqh, *pql, *pxh, *pxl, *pah, *pal, *phh, *phl, *pwh, *pwl;
    cudaGetSymbolAddress((void**)&px,   g_x);
    cudaGetSymbolAddress((void**)&pt,   g_t);
    cudaGetSymbolAddress((void**)&pqh,  g_qh);
    cudaGetSymbolAddress((void**)&pql,  g_ql);
    cudaGetSymbolAddress((void**)&pxh,  g_xh);
    cudaGetSymbolAddress((void**)&pxl,  g_xl);
    cudaGetSymbolAddress((void**)&pah,  g_ah);
    cudaGetSymbolAddress((void**)&pal,  g_al);
    cudaGetSymbolAddress((void**)&phh,  g_hh);
    cudaGetSymbolAddress((void**)&phl,  g_hl);
    cudaGetSymbolAddress((void**)&pwh,  g_wth);
    cudaGetSymbolAddress((void**)&pwl,  g_wtl);

    const int GSM = 2 * STG_B;   // 80 KB
    cudaFuncSetAttribute(gemm_mma<1>, cudaFuncAttributeMaxDynamicSharedMemorySize, GSM);
    cudaFuncSetAttribute(gemm_mma<2>, cudaFuncAttributeMaxDynamicSharedMemorySize, GSM);
    cudaFuncSetAttribute(gemm_mma<3>, cudaFuncAttributeMaxDynamicSharedMemorySize, GSM);
    cudaFuncSetAttribute(attn_mma, cudaFuncAttributeMaxDynamicSharedMemorySize, A_TOT);

    // weight transpose + bf16 split (all layers)
    transpose_split_kernel<<<dim3(1536/32, 512/32, L_), dim3(32,8)>>>(Wqkv, pwh, pwl, 512, 1536, OFF_QKV);
    transpose_split_kernel<<<dim3( 512/32, 512/32, L_), dim3(32,8)>>>(Wfc,  pwh, pwl, 512,  512, OFF_FC);
    transpose_split_kernel<<<dim3(2048/32, 512/32, L_), dim3(32,8)>>>(W1,   pwh, pwl, 512, 2048, OFF_W1);
    transpose_split_kernel<<<dim3( 512/32,2048/32, L_), dim3(32,8)>>>(W2,   pwh, pwl, 2048, 512, OFF_W2);

    // position embedding
    pos_scan_kernel<<<B_, S_>>>(mask);
    add_pos_kernel<<<(M_*D_)/256, 256>>>(x_in);

    for (int l = 0; l < L_; l++) {
        const unsigned short* wqh = pwh + (size_t)l*WT_L + OFF_QKV;
        const unsigned short* wql = pwl + (size_t)l*WT_L + OFF_QKV;
        const unsigned short* wfh = pwh + (size_t)l*WT_L + OFF_FC;
        const unsigned short* wfl = pwl + (size_t)l*WT_L + OFF_FC;
        const unsigned short* w1h = pwh + (size_t)l*WT_L + OFF_W1;
        const unsigned short* w1l = pwl + (size_t)l*WT_L + OFF_W1;
        const unsigned short* w2h = pwh + (size_t)l*WT_L + OFF_W2;
        const unsigned short* w2l = pwl + (size_t)l*WT_L + OFF_W2;

        // qkv = x @ Wqkv  [8192,512]x[512,1536] -> bf16 hi/lo
        gemm_mma<3><<<dim3(12, 64), 256, GSM>>>(pxh, pxl, wqh, wql,
            nullptr, nullptr, nullptr, pqh, pql, 3*D_, D_);

        // attention (tensor-core flash, direct-exp) -> att bf16 hi/lo
        attn_mma<<<dim3(S_/128, B_*H_), 256, A_TOT>>>(pqh, pql, mask, pah, pal);

        // o @ Wfc + bfc + residual(x) -> t ; LN1 -> x (+hi/lo)
        gemm_mma<1><<<dim3(4, 64), 256, GSM>>>(pah, pal, wfh, wfl,
            bfc + (size_t)l*D_, px, pt, nullptr, nullptr, D_, D_);
        ln_kernel<true><<<M_, 256>>>(pt, ln1g + (size_t)l*D_, ln1b + (size_t)l*D_,
                                     px, pxh, pxl);

        // h = relu(x @ W1 + b1) -> bf16 hi/lo
        gemm_mma<2><<<dim3(16, 64), 256, GSM>>>(pxh, pxl, w1h, w1l,
            b1 + (size_t)l*FF_, nullptr, nullptr, phh, phl, FF_, D_);

        // h @ W2 + b2 + residual(x) -> t ; LN2 -> x (+hi/lo) or d_out
        gemm_mma<1><<<dim3(4, 64), 256, GSM>>>(phh, phl, w2h, w2l,
            b2 + (size_t)l*D_, px, pt, nullptr, nullptr, D_, FF_);
        if (l == L_-1)
            ln_kernel<false><<<M_, 256>>>(pt, ln2g + (size_t)l*D_, ln2b + (size_t)l*D_,
                                          out, nullptr, nullptr);
        else
            ln_kernel<true><<<M_, 256>>>(pt, ln2g + (size_t)l*D_, ln2b + (size_t)l*D_,
                                         px, pxh, pxl);
    }
}

// round 12
// speedup vs baseline: 1.8400x; 1.6853x over previous
#include <cuda_runtime.h>
#include <cuda_bf16.h>
#include <cuda_fp16.h>
#include <math.h>
#include <stdint.h>

// Problem constants
#define B_  8
#define S_  1024
#define D_  512
#define H_  8
#define DH  64
#define FF_ 2048
#define L_  6
#define M_  (B_*S_)   // 8192 rows

// Transposed-weight layout (fp16), per layer (element offsets):
#define OFF_QKV 0
#define OFF_FC  786432
#define OFF_W1  1048576
#define OFF_W2  2097152
#define WT_L    3145728
#define WT_TOT  (WT_L*L_)

// ---------------- scratch (static device globals; no allocation) ----------------
__device__ float g_x[M_*D_];                 // fp32 activations (residual stream)
__device__ float g_t[M_*D_];                 // pre-LN temp
__device__ unsigned short g_qh[M_*3*D_], g_ql[M_*3*D_]; // qkv bf16 hi/lo (attention)
__device__ unsigned short g_xf[M_*D_];       // x fp16 (GEMM A operand)
__device__ unsigned short g_af[M_*D_];       // attention out fp16
__device__ unsigned short g_hf[M_*FF_];      // ffn hidden fp16
__device__ unsigned short g_wt[WT_TOT];      // transposed weights fp16
__device__ int g_pos[M_];

// ============================================================================
// helpers (baseline sm_80+ PTX only — no tcgen05 on this toolchain target)
// ============================================================================
__device__ __forceinline__ uint32_t su32(const void* p) {
    uint32_t a;
    asm("{ .reg .u64 t; cvta.to.shared.u64 t, %1; cvt.u32.u64 %0, t; }"
        : "=r"(a) : "l"(p));
    return a;
}

__device__ __forceinline__ void cp16(uint32_t s, const void* g) {
    asm volatile("cp.async.cg.shared.global [%0], [%1], 16;" :: "r"(s), "l"(g) : "memory");
}

__device__ __forceinline__ void ldsm4(uint32_t* r, uint32_t addr) {
    asm volatile("ldmatrix.sync.aligned.m8n8.x4.shared.b16 {%0,%1,%2,%3}, [%4];"
        : "=r"(r[0]), "=r"(r[1]), "=r"(r[2]), "=r"(r[3]) : "r"(addr));
}

__device__ __forceinline__ void ldsm4t(uint32_t* r, uint32_t addr) {
    asm volatile("ldmatrix.sync.aligned.m8n8.x4.trans.shared.b16 {%0,%1,%2,%3}, [%4];"
        : "=r"(r[0]), "=r"(r[1]), "=r"(r[2]), "=r"(r[3]) : "r"(addr));
}

__device__ __forceinline__ void mma_bf16(float* c, const uint32_t* a, const uint32_t* b) {
    asm volatile(
        "mma.sync.aligned.m16n8k16.row.col.f32.bf16.bf16.f32 "
        "{%0,%1,%2,%3}, {%4,%5,%6,%7}, {%8,%9}, {%0,%1,%2,%3};"
        : "+f"(c[0]), "+f"(c[1]), "+f"(c[2]), "+f"(c[3])
        : "r"(a[0]), "r"(a[1]), "r"(a[2]), "r"(a[3]), "r"(b[0]), "r"(b[1]));
}

__device__ __forceinline__ void mma_f16(float* c, const uint32_t* a, const uint32_t* b) {
    asm volatile(
        "mma.sync.aligned.m16n8k16.row.col.f32.f16.f16.f32 "
        "{%0,%1,%2,%3}, {%4,%5,%6,%7}, {%8,%9}, {%0,%1,%2,%3};"
        : "+f"(c[0]), "+f"(c[1]), "+f"(c[2]), "+f"(c[3])
        : "r"(a[0]), "r"(a[1]), "r"(a[2]), "r"(a[3]), "r"(b[0]), "r"(b[1]));
}

__device__ __forceinline__ void bf16_split(float v, unsigned short& hi, unsigned short& lo) {
    __nv_bfloat16 h = __float2bfloat16(v);
    hi = __bfloat16_as_ushort(h);
    lo = __bfloat16_as_ushort(__float2bfloat16(v - __bfloat162float(h)));
}

__device__ __forceinline__ unsigned short f16u(float v) {
    return __half_as_ushort(__float2half_rn(v));
}

// ============================================================================
// Position scan
// ============================================================================
__global__ void pos_scan_kernel(const int* __restrict__ mask)
{
    __shared__ int sc[S_];
    int b = blockIdx.x;
    int t = threadIdx.x;
    int v = (mask[b*S_ + t] != 0) ? 1 : 0;
    sc[t] = v;
    __syncthreads();
    for (int off = 1; off < S_; off <<= 1) {
        int add = (t >= off) ? sc[t - off] : 0;
        __syncthreads();
        sc[t] += add;
        __syncthreads();
    }
    g_pos[b*S_ + t] = v ? sc[t] : 0;
}

// ============================================================================
// x = x_in + sin_table[pos]; emit fp32 + fp16
// ============================================================================
__global__ void add_pos_kernel(const float* __restrict__ xin)
{
    int idx = blockIdx.x * 256 + threadIdx.x;
    int d = idx & (D_-1);
    int row = idx >> 9;
    int pos = g_pos[row];
    float e = 0.f;
    if (pos > 0) {
        const float c = -9.210340371976184f / 255.0f;
        if (d < 256) e = sinf((float)pos * expf((float)d * c));
        else         e = cosf((float)pos * expf((float)(d - 256) * c));
    }
    float v = xin[idx] + e;
    g_x[idx] = v;
    g_xf[idx] = f16u(v);
}

// ============================================================================
// Weight transpose + fp16 convert: W[K,N] -> T [N,K]  (grid.z = layer)
// ============================================================================
__global__ void transpose_f16_kernel(const float* __restrict__ W,
                                     unsigned short* __restrict__ Th,
                                     int K, int N, size_t out_off)
{
    __shared__ float t[32][33];
    int l = blockIdx.z;
    const float* Wp = W + (size_t)l * K * N;
    unsigned short* Thp = Th + (size_t)l * WT_L + out_off;
    int n0 = blockIdx.x * 32, k0 = blockIdx.y * 32;
    int tx = threadIdx.x, ty = threadIdx.y;   // 32 x 8
    #pragma unroll
    for (int i = 0; i < 4; i++)
        t[ty + 8*i][tx] = Wp[(size_t)(k0 + ty + 8*i) * N + n0 + tx];
    __syncthreads();
    #pragma unroll
    for (int i = 0; i < 4; i++) {
        float v = t[tx][ty + 8*i];
        Thp[(size_t)(n0 + ty + 8*i) * K + k0 + tx] = f16u(v);
    }
}

// ============================================================================
// mma.sync fp16 GEMM (single term): C[M,N] = A[M,K] @ B^T (B [N,K] fp16 rows)
// fp32 accum. CTA 128x128, BK=32, 256 thr, 8 warps (2x4) of 64x32,
// cp.async double buffer (proven 2-stage structure, now 40KB).
// EPI: 1 = +bias +Res fp32 out; 2 = relu(+bias) -> fp16; 3 = plain -> bf16 hi/lo
// ============================================================================
#define BK 32
#define ROW_B 80            // smem row stride bytes (64B data + 16B pad)
#define TEN_B 10240         // 128 rows * 80B
#define STG_B (2*TEN_B)     // A + B per stage

template<int EPI>
__global__ void __launch_bounds__(256)
gemm_mma(const unsigned short* __restrict__ A, const unsigned short* __restrict__ Bw,
         const float* __restrict__ bias, const float* __restrict__ Res,
         float* __restrict__ Cf,
         unsigned short* __restrict__ Ch, unsigned short* __restrict__ Cl,
         int N, int K)
{
    extern __shared__ __align__(16) char smem[];
    const uint32_t sb = su32(smem);
    const int tid = threadIdx.x;
    const int lane = tid & 31, wid = tid >> 5;
    const int wm = wid & 1, wn = wid >> 1;
    const int m0 = blockIdx.y * 128, n0 = blockIdx.x * 128;

    float acc[4][4][4];
    #pragma unroll
    for (int i = 0; i < 4; i++)
        #pragma unroll
        for (int j = 0; j < 4; j++)
            #pragma unroll
            for (int k = 0; k < 4; k++) acc[i][j][k] = 0.f;

    const int nc = K / BK;

    // ---- chunk loader (4 cp.async of 16B per thread) ----
    auto load_chunk = [&](int c, int stage) {
        const uint32_t st = sb + stage * STG_B;
        const int k0 = c * BK;
        #pragma unroll
        for (int j = 0; j < 2; j++) {
            int idx = tid * 2 + j;          // 0..511
            int r = idx >> 2, sg = idx & 3;
            uint32_t so = r * ROW_B + sg * 16;
            cp16(st +         so, A  + (size_t)(m0 + r) * K + k0 + sg * 8);
            cp16(st + TEN_B + so, Bw + (size_t)(n0 + r) * K + k0 + sg * 8);
        }
        asm volatile("cp.async.commit_group;" ::: "memory");
    };

    // ---- chunk compute (single-term fp16) ----
    auto compute_chunk = [&](int stage) {
        const uint32_t st = sb + stage * STG_B;
        const uint32_t lrow = (lane & 15);
        const uint32_t lcol = (lane >> 4) * 16;
        #pragma unroll
        for (int ks = 0; ks < 2; ks++) {
            const uint32_t kb = ks * 32 + lcol;
            uint32_t aF[4][4], bF[4][2];
            #pragma unroll
            for (int mt = 0; mt < 4; mt++)
                ldsm4(aF[mt], st + (wm*64 + mt*16 + lrow) * ROW_B + kb);
            #pragma unroll
            for (int g = 0; g < 2; g++) {
                uint32_t t0[4];
                ldsm4(t0, st + TEN_B + (wn*32 + g*16 + lrow) * ROW_B + kb);
                bF[g*2][0]   = t0[0]; bF[g*2][1]   = t0[2];
                bF[g*2+1][0] = t0[1]; bF[g*2+1][1] = t0[3];
            }
            #pragma unroll
            for (int mt = 0; mt < 4; mt++)
                #pragma unroll
                for (int nt = 0; nt < 4; nt++)
                    mma_f16(acc[mt][nt], aF[mt], bF[nt]);
        }
    };

    load_chunk(0, 0);
    for (int c = 0; c < nc; c++) {
        if (c + 1 < nc) {
            load_chunk(c + 1, (c + 1) & 1);
            asm volatile("cp.async.wait_group 1;" ::: "memory");
        } else {
            asm volatile("cp.async.wait_group 0;" ::: "memory");
        }
        __syncthreads();
        compute_chunk(c & 1);
        __syncthreads();
    }

    // ---- epilogue ----
    const int r0 = lane >> 2;
    const int cp = (lane & 3) * 2;
    #pragma unroll
    for (int mt = 0; mt < 4; mt++) {
        #pragma unroll
        for (int half = 0; half < 2; half++) {
            const size_t row = (size_t)(m0 + wm*64 + mt*16 + half*8 + r0);
            #pragma unroll
            for (int nt = 0; nt < 4; nt++) {
                const int col = n0 + wn*32 + nt*8 + cp;
                float v0 = acc[mt][nt][half*2 + 0];
                float v1 = acc[mt][nt][half*2 + 1];
                if (EPI == 1) {
                    float2 bb = *(const float2*)&bias[col];
                    float2 rr = *(const float2*)&Res[row*N + col];
                    float2 o; o.x = v0 + bb.x + rr.x; o.y = v1 + bb.y + rr.y;
                    *(float2*)&Cf[row*N + col] = o;
                } else if (EPI == 2) {
                    float2 bb = *(const float2*)&bias[col];
                    v0 = fmaxf(v0 + bb.x, 0.f);
                    v1 = fmaxf(v1 + bb.y, 0.f);
                    ushort2 ff; ff.x = f16u(v0); ff.y = f16u(v1);
                    *(ushort2*)&Ch[row*N + col] = ff;
                } else {   // EPI == 3 : bf16 hi/lo pair (attention input)
                    ushort2 hh, ll;
                    bf16_split(v0, hh.x, ll.x);
                    bf16_split(v1, hh.y, ll.y);
                    *(ushort2*)&Ch[row*N + col] = hh;
                    *(ushort2*)&Cl[row*N + col] = ll;
                }
            }
        }
    }
}

// ============================================================================
// Flash attention via mma.sync bf16 (hi/lo split, 3-term): scale = 1.
// DIRECT-EXP softmax (bf16 range needed: p up to e^{~20} overflows fp16).
// Row-sum l in registers, single normalization at the end. Output fp16.
// CTA: 128 q-rows x full S keys (64-key tiles). 256 thr, warps 4(m) x 2(n).
// ============================================================================
#define AST 144                 // smem row stride bytes (64 bf16 + 16B pad)
#define A_QH 0
#define A_QL 18432
#define A_KH 36864              // + stage*9216
#define A_KL 55296
#define A_VH 73728
#define A_VL 92160
#define A_PH 110592             // single-buffered (sync-protected)
#define A_PL 129024
#define A_LR 147456             // float[2][128] final l exchange
#define A_KM 148480             // int[2][64] mask
#define A_TOT 149504

__global__ void __launch_bounds__(256)
attn_mma(const unsigned short* __restrict__ qh, const unsigned short* __restrict__ ql,
         const int* __restrict__ mask,
         unsigned short* __restrict__ outf)
{
    extern __shared__ __align__(16) char asmem[];
    const uint32_t sb = su32(asmem);
    float* lred = (float*)(asmem + A_LR);
    int*   kvm  = (int*)  (asmem + A_KM);

    const int tid = threadIdx.x, lane = tid & 31, wid = tid >> 5;
    const int wm = wid & 3, wn = wid >> 2;
    const int q0 = blockIdx.x * 128;
    const int b  = blockIdx.y >> 3;
    const int h  = blockIdx.y & 7;
    const int RS = 3 * D_;

    // ---- load Q tile [128][64] hi/lo ----
    {
        const int r_ = tid >> 3, sg = tid & 7;
        #pragma unroll
        for (int i = 0; i < 4; i++) {
            int r = r_ + 32*i;
            size_t g = (size_t)(b*S_ + q0 + r)*RS + h*DH + sg*8;
            cp16(sb + A_QH + r*AST + sg*16, qh + g);
            cp16(sb + A_QL + r*AST + sg*16, ql + g);
        }
    }

    // ---- KV tile loader ----
    auto load_kv = [&](int j, int s) {
        const int r_ = tid >> 3, sg = tid & 7;
        #pragma unroll
        for (int i = 0; i < 2; i++) {
            int r = r_ + 32*i;
            size_t gk = (size_t)(b*S_ + j*64 + r)*RS + D_   + h*DH + sg*8;
            size_t gv = (size_t)(b*S_ + j*64 + r)*RS + 2*D_ + h*DH + sg*8;
            uint32_t so = s*9216 + r*AST + sg*16;
            cp16(sb + A_KH + so, qh + gk);
            cp16(sb + A_KL + so, ql + gk);
            cp16(sb + A_VH + so, qh + gv);
            cp16(sb + A_VL + so, ql + gv);
        }
        if (tid < 64) kvm[s*64 + tid] = mask[b*S_ + j*64 + tid];
        asm volatile("cp.async.commit_group;" ::: "memory");
    };
    load_kv(0, 0);

    float oacc[2][4][4];
    #pragma unroll
    for (int i = 0; i < 2; i++)
        #pragma unroll
        for (int j = 0; j < 4; j++)
            #pragma unroll
            for (int k = 0; k < 4; k++) oacc[i][j][k] = 0.f;
    float lreg[2][2] = {{0.f, 0.f}, {0.f, 0.f}};

    const uint32_t lrow = lane & 15;
    const uint32_t lcol = (lane >> 4) * 16;
    const int qr  = lane >> 2;        // row-within-8 for C fragments
    const int cc2 = (lane & 3) * 2;   // col pair base

    for (int j = 0; j < S_/64; j++) {
        const int s = j & 1;
        asm volatile("cp.async.wait_group 0;" ::: "memory");
        __syncthreads();
        if (j + 1 < S_/64) load_kv(j + 1, s ^ 1);

        // ---- S = Q K^T (3-term split) ----
        float sacc[2][4][4];
        #pragma unroll
        for (int i = 0; i < 2; i++)
            #pragma unroll
            for (int jj = 0; jj < 4; jj++)
                #pragma unroll
                for (int k = 0; k < 4; k++) sacc[i][jj][k] = 0.f;

        #pragma unroll
        for (int ks = 0; ks < 4; ks++) {           // dh = 64 -> 4 k16 steps
            const uint32_t kb = ks*32 + lcol;
            uint32_t aH[2][4], aL[2][4], bH[4][2], bL[4][2];
            #pragma unroll
            for (int mt = 0; mt < 2; mt++) {
                uint32_t ad = sb + (wm*32 + mt*16 + lrow)*AST + kb;
                ldsm4(aH[mt], ad + A_QH);
                ldsm4(aL[mt], ad + A_QL);
            }
            #pragma unroll
            for (int g = 0; g < 2; g++) {
                uint32_t bd = sb + s*9216 + (wn*32 + g*16 + lrow)*AST + kb;
                uint32_t t0[4], t1[4];
                ldsm4(t0, bd + A_KH);
                ldsm4(t1, bd + A_KL);
                bH[g*2][0] = t0[0]; bH[g*2][1] = t0[2];
                bH[g*2+1][0] = t0[1]; bH[g*2+1][1] = t0[3];
                bL[g*2][0] = t1[0]; bL[g*2][1] = t1[2];
                bL[g*2+1][0] = t1[1]; bL[g*2+1][1] = t1[3];
            }
            #pragma unroll
            for (int mt = 0; mt < 2; mt++)
                #pragma unroll
                for (int nt = 0; nt < 4; nt++) {
                    mma_bf16(sacc[mt][nt], aH[mt], bH[nt]);
                    mma_bf16(sacc[mt][nt], aH[mt], bL[nt]);
                    mma_bf16(sacc[mt][nt], aL[mt], bH[nt]);
                }
        }

        // ---- direct exp + mask, register l accumulation, P store ----
        #pragma unroll
        for (int nt = 0; nt < 4; nt++) {
            int col = wn*32 + nt*8 + cc2;
            const bool live0 = (kvm[s*64 + col]     != 0);
            const bool live1 = (kvm[s*64 + col + 1] != 0);
            #pragma unroll
            for (int mt = 0; mt < 2; mt++)
                #pragma unroll
                for (int half = 0; half < 2; half++) {
                    float p0 = live0 ? __expf(sacc[mt][nt][2*half])   : 0.f;
                    float p1 = live1 ? __expf(sacc[mt][nt][2*half+1]) : 0.f;
                    lreg[mt][half] += p0 + p1;
                    int row = wm*32 + mt*16 + half*8 + qr;
                    ushort2 hh, ll;
                    bf16_split(p0, hh.x, ll.x);
                    bf16_split(p1, hh.y, ll.y);
                    uint32_t po = row*AST + col*2;
                    *(ushort2*)(asmem + A_PH + po) = hh;
                    *(ushort2*)(asmem + A_PL + po) = ll;
                }
        }
        __syncthreads();

        // ---- O += P V (3-term split) ----
        #pragma unroll
        for (int ks = 0; ks < 4; ks++) {           // 64 keys -> 4 k16 steps
            const uint32_t kb = ks*32 + lcol;
            uint32_t pHf[2][4], pLf[2][4], vHf[4][2], vLf[4][2];
            #pragma unroll
            for (int mt = 0; mt < 2; mt++) {
                uint32_t ad = sb + (wm*32 + mt*16 + lrow)*AST + kb;
                ldsm4(pHf[mt], ad + A_PH);
                ldsm4(pLf[mt], ad + A_PL);
            }
            #pragma unroll
            for (int g = 0; g < 2; g++) {
                uint32_t va = sb + s*9216
                            + (ks*16 + (lane & 7) + 8*((lane >> 3) & 1))*AST
                            + (wn*32 + g*16 + 8*(lane >> 4))*2;
                uint32_t t0[4], t1[4];
                ldsm4t(t0, va + A_VH);
                ldsm4t(t1, va + A_VL);
                vHf[g*2][0] = t0[0]; vHf[g*2][1] = t0[1];
                vHf[g*2+1][0] = t0[2]; vHf[g*2+1][1] = t0[3];
                vLf[g*2][0] = t1[0]; vLf[g*2][1] = t1[1];
                vLf[g*2+1][0] = t1[2]; vLf[g*2+1][1] = t1[3];
            }
            #pragma unroll
            for (int mt = 0; mt < 2; mt++)
                #pragma unroll
                for (int nt = 0; nt < 4; nt++) {
                    mma_bf16(oacc[mt][nt], pHf[mt], vHf[nt]);
                    mma_bf16(oacc[mt][nt], pHf[mt], vLf[nt]);
                    mma_bf16(oacc[mt][nt], pLf[mt], vHf[nt]);
                }
        }
    }

    // ---- final l reduction: lane group, then across wn via smem ----
    #pragma unroll
    for (int mt = 0; mt < 2; mt++)
        #pragma unroll
        for (int half = 0; half < 2; half++) {
            float v = lreg[mt][half];
            v += __shfl_xor_sync(0xffffffffu, v, 1);
            v += __shfl_xor_sync(0xffffffffu, v, 2);
            lreg[mt][half] = v;
        }
    __syncthreads();   // P buffer reads done; lred region free
    if ((lane & 3) == 0) {
        #pragma unroll
        for (int mt = 0; mt < 2; mt++)
            #pragma unroll
            for (int half = 0; half < 2; half++) {
                int row = wm*32 + mt*16 + half*8 + qr;
                lred[wn*128 + row] = lreg[mt][half];
            }
    }
    __syncthreads();

    // ---- finalize: divide by l, write fp16 ----
    #pragma unroll
    for (int mt = 0; mt < 2; mt++)
        #pragma unroll
        for (int half = 0; half < 2; half++) {
            int row = wm*32 + mt*16 + half*8 + qr;
            float linv = 1.f / (lred[row] + lred[128 + row]);
            size_t base = (size_t)(b*S_ + q0 + row)*D_ + h*DH;
            #pragma unroll
            for (int nt = 0; nt < 4; nt++) {
                int d = wn*32 + nt*8 + cc2;
                float w0 = oacc[mt][nt][2*half]   * linv;
                float w1 = oacc[mt][nt][2*half+1] * linv;
                ushort2 ff; ff.x = f16u(w0); ff.y = f16u(w1);
                *(ushort2*)&outf[base + d] = ff;
            }
        }
}

// ============================================================================
// LayerNorm over last dim (512); optional fp16 side output
// ============================================================================
template<bool EMIT16>
__global__ void __launch_bounds__(256)
ln_kernel(const float* __restrict__ X, const float* __restrict__ g,
          const float* __restrict__ bta, float* __restrict__ Y,
          unsigned short* __restrict__ Yf)
{
    __shared__ float red[32];
    const int row = blockIdx.x;
    const int t = threadIdx.x;
    const int lane = t & 31, w = t >> 5;

    float2 v = ((const float2*)(X + (size_t)row*D_))[t];

    float s = v.x + v.y;
    #pragma unroll
    for (int o = 16; o; o >>= 1) s += __shfl_xor_sync(0xffffffffu, s, o);
    if (lane == 0) red[w] = s;
    __syncthreads();
    if (t < 32) {
        float a = (t < 8) ? red[t] : 0.f;
        #pragma unroll
        for (int o = 4; o; o >>= 1) a += __shfl_xor_sync(0xffffffffu, a, o);
        if (t == 0) red[0] = a;
    }
    __syncthreads();
    const float mu = red[0] * (1.f / D_);
    __syncthreads();

    float d0 = v.x - mu, d1 = v.y - mu;
    float q = d0*d0 + d1*d1;
    #pragma unroll
    for (int o = 16; o; o >>= 1) q += __shfl_xor_sync(0xffffffffu, q, o);
    if (lane == 0) red[w] = q;
    __syncthreads();
    if (t < 32) {
        float a = (t < 8) ? red[t] : 0.f;
        #pragma unroll
        for (int o = 4; o; o >>= 1) a += __shfl_xor_sync(0xffffffffu, a, o);
        if (t == 0) red[0] = a;
    }
    __syncthreads();
    const float var = red[0] * (1.f / D_);
    const float inv = rsqrtf(var + 1e-5f);

    float2 gv = ((const float2*)g)[t];
    float2 bv = ((const float2*)bta)[t];
    float y0 = d0 * inv * gv.x + bv.x;
    float y1 = d1 * inv * gv.y + bv.y;
    float2 o2; o2.x = y0; o2.y = y1;
    ((float2*)(Y + (size_t)row*D_))[t] = o2;
    if (EMIT16) {
        ushort2 ff; ff.x = f16u(y0); ff.y = f16u(y1);
        ((ushort2*)(Yf + (size_t)row*D_))[t] = ff;
    }
}

// ============================================================================
// Host launcher
// ============================================================================
extern "C" void kernel_launch(void* const* d_in, const int* in_sizes, int n_in,
                              void* d_out, int out_size)
{
    const float* x_in  = (const float*)d_in[0];
    const int*   mask  = (const int*)d_in[3];
    const float* Wqkv  = (const float*)d_in[4];
    const float* Wfc   = (const float*)d_in[5];
    const float* bfc   = (const float*)d_in[6];
    const float* ln1g  = (const float*)d_in[7];
    const float* ln1b  = (const float*)d_in[8];
    const float* ln2g  = (const float*)d_in[9];
    const float* ln2b  = (const float*)d_in[10];
    const float* W1    = (const float*)d_in[11];
    const float* b1    = (const float*)d_in[12];
    const float* W2    = (const float*)d_in[13];
    const float* b2    = (const float*)d_in[14];
    float* out = (float*)d_out;

    float *px, *pt;
    unsigned short *pqh, *pql, *pxf, *paf, *phf, *pwt;
    cudaGetSymbolAddress((void**)&px,   g_x);
    cudaGetSymbolAddress((void**)&pt,   g_t);
    cudaGetSymbolAddress((void**)&pqh,  g_qh);
    cudaGetSymbolAddress((void**)&pql,  g_ql);
    cudaGetSymbolAddress((void**)&pxf,  g_xf);
    cudaGetSymbolAddress((void**)&paf,  g_af);
    cudaGetSymbolAddress((void**)&phf,  g_hf);
    cudaGetSymbolAddress((void**)&pwt,  g_wt);

    const int GSM = 2 * STG_B;   // 40 KB
    cudaFuncSetAttribute(gemm_mma<1>, cudaFuncAttributeMaxDynamicSharedMemorySize, GSM);
    cudaFuncSetAttribute(gemm_mma<2>, cudaFuncAttributeMaxDynamicSharedMemorySize, GSM);
    cudaFuncSetAttribute(gemm_mma<3>, cudaFuncAttributeMaxDynamicSharedMemorySize, GSM);
    cudaFuncSetAttribute(attn_mma, cudaFuncAttributeMaxDynamicSharedMemorySize, A_TOT);

    // weight transpose + fp16 convert (all layers)
    transpose_f16_kernel<<<dim3(1536/32, 512/32, L_), dim3(32,8)>>>(Wqkv, pwt, 512, 1536, OFF_QKV);
    transpose_f16_kernel<<<dim3( 512/32, 512/32, L_), dim3(32,8)>>>(Wfc,  pwt, 512,  512, OFF_FC);
    transpose_f16_kernel<<<dim3(2048/32, 512/32, L_), dim3(32,8)>>>(W1,   pwt, 512, 2048, OFF_W1);
    transpose_f16_kernel<<<dim3( 512/32,2048/32, L_), dim3(32,8)>>>(W2,   pwt, 2048, 512, OFF_W2);

    // position embedding
    pos_scan_kernel<<<B_, S_>>>(mask);
    add_pos_kernel<<<(M_*D_)/256, 256>>>(x_in);

    for (int l = 0; l < L_; l++) {
        const unsigned short* wq = pwt + (size_t)l*WT_L + OFF_QKV;
        const unsigned short* wf = pwt + (size_t)l*WT_L + OFF_FC;
        const unsigned short* w1 = pwt + (size_t)l*WT_L + OFF_W1;
        const unsigned short* w2 = pwt + (size_t)l*WT_L + OFF_W2;

        // qkv = x @ Wqkv  [8192,512]x[512,1536] -> bf16 hi/lo (attention input)
        gemm_mma<3><<<dim3(12, 64), 256, GSM>>>(pxf, wq,
            nullptr, nullptr, nullptr, pqh, pql, 3*D_, D_);

        // attention (tensor-core flash, direct-exp) -> fp16
        attn_mma<<<dim3(S_/128, B_*H_), 256, A_TOT>>>(pqh, pql, mask, paf);

        // o @ Wfc + bfc + residual(x) -> t ; LN1 -> x (+fp16)
        gemm_mma<1><<<dim3(4, 64), 256, GSM>>>(paf, wf,
            bfc + (size_t)l*D_, px, pt, nullptr, nullptr, D_, D_);
        ln_kernel<true><<<M_, 256>>>(pt, ln1g + (size_t)l*D_, ln1b + (size_t)l*D_,
                                     px, pxf);

        // h = relu(x @ W1 + b1) -> fp16
        gemm_mma<2><<<dim3(16, 64), 256, GSM>>>(pxf, w1,
            b1 + (size_t)l*FF_, nullptr, nullptr, phf, nullptr, FF_, D_);

        // h @ W2 + b2 + residual(x) -> t ; LN2 -> x (+fp16) or d_out
        gemm_mma<1><<<dim3(4, 64), 256, GSM>>>(phf, w2,
            b2 + (size_t)l*D_, px, pt, nullptr, nullptr, D_, FF_);
        if (l == L_-1)
            ln_kernel<false><<<M_, 256>>>(pt, ln2g + (size_t)l*D_, ln2b + (size_t)l*D_,
                                          out, nullptr);
        else
            ln_kernel<true><<<M_, 256>>>(pt, ln2g + (size_t)l*D_, ln2b + (size_t)l*D_,
                                         px, pxf);
    }
}

// round 13
// speedup vs baseline: 2.0817x; 1.1314x over previous
#include <cuda_runtime.h>
#include <cuda_bf16.h>
#include <cuda_fp16.h>
#include <math.h>
#include <stdint.h>

// Problem constants
#define B_  8
#define S_  1024
#define D_  512
#define H_  8
#define DH  64
#define FF_ 2048
#define L_  6
#define M_  (B_*S_)   // 8192 rows

// Transposed-weight layout (fp16), per layer (element offsets):
#define OFF_QKV 0
#define OFF_FC  786432
#define OFF_W1  1048576
#define OFF_W2  2097152
#define WT_L    3145728
#define WT_TOT  (WT_L*L_)

// ---------------- scratch (static device globals; no allocation) ----------------
__device__ float g_x[M_*D_];                 // fp32 activations (residual stream)
__device__ float g_t[M_*D_];                 // pre-LN temp
__device__ unsigned short g_qf[M_*3*D_];     // qkv fp16 (Q,K region used)
__device__ unsigned short g_qh[M_*3*D_], g_ql[M_*3*D_]; // qkv bf16 hi/lo (V region used)
__device__ unsigned short g_xf[M_*D_];       // x fp16 (GEMM A operand)
__device__ unsigned short g_af[M_*D_];       // attention out fp16
__device__ unsigned short g_hf[M_*FF_];      // ffn hidden fp16
__device__ unsigned short g_wt[WT_TOT];      // transposed weights fp16
__device__ int g_pos[M_];

// ============================================================================
// helpers (baseline sm_80+ PTX only — no tcgen05 on this toolchain target)
// ============================================================================
__device__ __forceinline__ uint32_t su32(const void* p) {
    uint32_t a;
    asm("{ .reg .u64 t; cvta.to.shared.u64 t, %1; cvt.u32.u64 %0, t; }"
        : "=r"(a) : "l"(p));
    return a;
}

__device__ __forceinline__ void cp16(uint32_t s, const void* g) {
    asm volatile("cp.async.cg.shared.global [%0], [%1], 16;" :: "r"(s), "l"(g) : "memory");
}

__device__ __forceinline__ void ldsm4(uint32_t* r, uint32_t addr) {
    asm volatile("ldmatrix.sync.aligned.m8n8.x4.shared.b16 {%0,%1,%2,%3}, [%4];"
        : "=r"(r[0]), "=r"(r[1]), "=r"(r[2]), "=r"(r[3]) : "r"(addr));
}

__device__ __forceinline__ void ldsm4t(uint32_t* r, uint32_t addr) {
    asm volatile("ldmatrix.sync.aligned.m8n8.x4.trans.shared.b16 {%0,%1,%2,%3}, [%4];"
        : "=r"(r[0]), "=r"(r[1]), "=r"(r[2]), "=r"(r[3]) : "r"(addr));
}

__device__ __forceinline__ void mma_bf16(float* c, const uint32_t* a, const uint32_t* b) {
    asm volatile(
        "mma.sync.aligned.m16n8k16.row.col.f32.bf16.bf16.f32 "
        "{%0,%1,%2,%3}, {%4,%5,%6,%7}, {%8,%9}, {%0,%1,%2,%3};"
        : "+f"(c[0]), "+f"(c[1]), "+f"(c[2]), "+f"(c[3])
        : "r"(a[0]), "r"(a[1]), "r"(a[2]), "r"(a[3]), "r"(b[0]), "r"(b[1]));
}

__device__ __forceinline__ void mma_f16(float* c, const uint32_t* a, const uint32_t* b) {
    asm volatile(
        "mma.sync.aligned.m16n8k16.row.col.f32.f16.f16.f32 "
        "{%0,%1,%2,%3}, {%4,%5,%6,%7}, {%8,%9}, {%0,%1,%2,%3};"
        : "+f"(c[0]), "+f"(c[1]), "+f"(c[2]), "+f"(c[3])
        : "r"(a[0]), "r"(a[1]), "r"(a[2]), "r"(a[3]), "r"(b[0]), "r"(b[1]));
}

__device__ __forceinline__ void bf16_split(float v, unsigned short& hi, unsigned short& lo) {
    __nv_bfloat16 h = __float2bfloat16(v);
    hi = __bfloat16_as_ushort(h);
    lo = __bfloat16_as_ushort(__float2bfloat16(v - __bfloat162float(h)));
}

__device__ __forceinline__ unsigned short f16u(float v) {
    return __half_as_ushort(__float2half_rn(v));
}

// ============================================================================
// Position scan
// ============================================================================
__global__ void pos_scan_kernel(const int* __restrict__ mask)
{
    __shared__ int sc[S_];
    int b = blockIdx.x;
    int t = threadIdx.x;
    int v = (mask[b*S_ + t] != 0) ? 1 : 0;
    sc[t] = v;
    __syncthreads();
    for (int off = 1; off < S_; off <<= 1) {
        int add = (t >= off) ? sc[t - off] : 0;
        __syncthreads();
        sc[t] += add;
        __syncthreads();
    }
    g_pos[b*S_ + t] = v ? sc[t] : 0;
}

// ============================================================================
// x = x_in + sin_table[pos]; emit fp32 + fp16
// ============================================================================
__global__ void add_pos_kernel(const float* __restrict__ xin)
{
    int idx = blockIdx.x * 256 + threadIdx.x;
    int d = idx & (D_-1);
    int row = idx >> 9;
    int pos = g_pos[row];
    float e = 0.f;
    if (pos > 0) {
        const float c = -9.210340371976184f / 255.0f;
        if (d < 256) e = sinf((float)pos * expf((float)d * c));
        else         e = cosf((float)pos * expf((float)(d - 256) * c));
    }
    float v = xin[idx] + e;
    g_x[idx] = v;
    g_xf[idx] = f16u(v);
}

// ============================================================================
// Weight transpose + fp16 convert: W[K,N] -> T [N,K]  (grid.z = layer)
// ============================================================================
__global__ void transpose_f16_kernel(const float* __restrict__ W,
                                     unsigned short* __restrict__ Th,
                                     int K, int N, size_t out_off)
{
    __shared__ float t[32][33];
    int l = blockIdx.z;
    const float* Wp = W + (size_t)l * K * N;
    unsigned short* Thp = Th + (size_t)l * WT_L + out_off;
    int n0 = blockIdx.x * 32, k0 = blockIdx.y * 32;
    int tx = threadIdx.x, ty = threadIdx.y;   // 32 x 8
    #pragma unroll
    for (int i = 0; i < 4; i++)
        t[ty + 8*i][tx] = Wp[(size_t)(k0 + ty + 8*i) * N + n0 + tx];
    __syncthreads();
    #pragma unroll
    for (int i = 0; i < 4; i++) {
        float v = t[tx][ty + 8*i];
        Thp[(size_t)(n0 + ty + 8*i) * K + k0 + tx] = f16u(v);
    }
}

// ============================================================================
// mma.sync fp16 GEMM (single term): C[M,N] = A[M,K] @ B^T (B [N,K] fp16 rows)
// fp32 accum. CTA 128x128, BK=32, 256 thr, 8 warps (2x4) of 64x32,
// cp.async double buffer (proven 2-stage structure, 40KB).
// EPI: 1 = +bias +Res fp32 out; 2 = relu(+bias) -> fp16;
//      3 = qkv: col<2D -> fp16 (Cq); col>=2D -> bf16 hi/lo (Ch/Cl)
// ============================================================================
#define BK 32
#define ROW_B 80            // smem row stride bytes (64B data + 16B pad)
#define TEN_B 10240         // 128 rows * 80B
#define STG_B (2*TEN_B)     // A + B per stage

template<int EPI>
__global__ void __launch_bounds__(256)
gemm_mma(const unsigned short* __restrict__ A, const unsigned short* __restrict__ Bw,
         const float* __restrict__ bias, const float* __restrict__ Res,
         float* __restrict__ Cf, unsigned short* __restrict__ Cq,
         unsigned short* __restrict__ Ch, unsigned short* __restrict__ Cl,
         int N, int K)
{
    extern __shared__ __align__(16) char smem[];
    const uint32_t sb = su32(smem);
    const int tid = threadIdx.x;
    const int lane = tid & 31, wid = tid >> 5;
    const int wm = wid & 1, wn = wid >> 1;
    const int m0 = blockIdx.y * 128, n0 = blockIdx.x * 128;

    float acc[4][4][4];
    #pragma unroll
    for (int i = 0; i < 4; i++)
        #pragma unroll
        for (int j = 0; j < 4; j++)
            #pragma unroll
            for (int k = 0; k < 4; k++) acc[i][j][k] = 0.f;

    const int nc = K / BK;

    auto load_chunk = [&](int c, int stage) {
        const uint32_t st = sb + stage * STG_B;
        const int k0 = c * BK;
        #pragma unroll
        for (int j = 0; j < 2; j++) {
            int idx = tid * 2 + j;          // 0..511
            int r = idx >> 2, sg = idx & 3;
            uint32_t so = r * ROW_B + sg * 16;
            cp16(st +         so, A  + (size_t)(m0 + r) * K + k0 + sg * 8);
            cp16(st + TEN_B + so, Bw + (size_t)(n0 + r) * K + k0 + sg * 8);
        }
        asm volatile("cp.async.commit_group;" ::: "memory");
    };

    auto compute_chunk = [&](int stage) {
        const uint32_t st = sb + stage * STG_B;
        const uint32_t lrow = (lane & 15);
        const uint32_t lcol = (lane >> 4) * 16;
        #pragma unroll
        for (int ks = 0; ks < 2; ks++) {
            const uint32_t kb = ks * 32 + lcol;
            uint32_t aF[4][4], bF[4][2];
            #pragma unroll
            for (int mt = 0; mt < 4; mt++)
                ldsm4(aF[mt], st + (wm*64 + mt*16 + lrow) * ROW_B + kb);
            #pragma unroll
            for (int g = 0; g < 2; g++) {
                uint32_t t0[4];
                ldsm4(t0, st + TEN_B + (wn*32 + g*16 + lrow) * ROW_B + kb);
                bF[g*2][0]   = t0[0]; bF[g*2][1]   = t0[2];
                bF[g*2+1][0] = t0[1]; bF[g*2+1][1] = t0[3];
            }
            #pragma unroll
            for (int mt = 0; mt < 4; mt++)
                #pragma unroll
                for (int nt = 0; nt < 4; nt++)
                    mma_f16(acc[mt][nt], aF[mt], bF[nt]);
        }
    };

    load_chunk(0, 0);
    for (int c = 0; c < nc; c++) {
        if (c + 1 < nc) {
            load_chunk(c + 1, (c + 1) & 1);
            asm volatile("cp.async.wait_group 1;" ::: "memory");
        } else {
            asm volatile("cp.async.wait_group 0;" ::: "memory");
        }
        __syncthreads();
        compute_chunk(c & 1);
        __syncthreads();
    }

    // ---- epilogue ----
    const int r0 = lane >> 2;
    const int cp = (lane & 3) * 2;
    #pragma unroll
    for (int mt = 0; mt < 4; mt++) {
        #pragma unroll
        for (int half = 0; half < 2; half++) {
            const size_t row = (size_t)(m0 + wm*64 + mt*16 + half*8 + r0);
            #pragma unroll
            for (int nt = 0; nt < 4; nt++) {
                const int col = n0 + wn*32 + nt*8 + cp;
                float v0 = acc[mt][nt][half*2 + 0];
                float v1 = acc[mt][nt][half*2 + 1];
                if (EPI == 1) {
                    float2 bb = *(const float2*)&bias[col];
                    float2 rr = *(const float2*)&Res[row*N + col];
                    float2 o; o.x = v0 + bb.x + rr.x; o.y = v1 + bb.y + rr.y;
                    *(float2*)&Cf[row*N + col] = o;
                } else if (EPI == 2) {
                    float2 bb = *(const float2*)&bias[col];
                    v0 = fmaxf(v0 + bb.x, 0.f);
                    v1 = fmaxf(v1 + bb.y, 0.f);
                    ushort2 ff; ff.x = f16u(v0); ff.y = f16u(v1);
                    *(ushort2*)&Ch[row*N + col] = ff;
                } else {   // EPI == 3 : qkv — Q,K cols as fp16; V cols as bf16 hi/lo
                    if (col < 2*D_) {
                        ushort2 ff; ff.x = f16u(v0); ff.y = f16u(v1);
                        *(ushort2*)&Cq[row*N + col] = ff;
                    } else {
                        ushort2 hh, ll;
                        bf16_split(v0, hh.x, ll.x);
                        bf16_split(v1, hh.y, ll.y);
                        *(ushort2*)&Ch[row*N + col] = hh;
                        *(ushort2*)&Cl[row*N + col] = ll;
                    }
                }
            }
        }
    }
}

// ============================================================================
// Flash attention: QK^T single-term fp16 (Q,K already fp16-noisy from qkv GEMM);
// PV 3-term bf16 split (P needs bf16 range: p = exp(s) unnormalized).
// DIRECT-EXP softmax, register l accumulation, final normalization. Output fp16.
// CTA: 128 q-rows x full S keys (64-key tiles). 256 thr, warps 4(m) x 2(n).
// ============================================================================
#define AST 144                 // smem row stride bytes (64 elems * 2B + 16B pad)
#define A_QF 0                  // Q fp16 [128][AST]           18432
#define A_KF 18432              // K fp16 + stage*9216         18432
#define A_VH 36864              // V bf16 hi + stage*9216      18432
#define A_VL 55296              // V bf16 lo + stage*9216      18432
#define A_PH 73728              // P bf16 hi (single-buffered) 18432
#define A_PL 92160              // P bf16 lo                   18432
#define A_LR 110592             // float[2][128] final l exchange
#define A_KM 111616             // int[2][64] mask
#define A_TOT 112128

__global__ void __launch_bounds__(256)
attn_mma(const unsigned short* __restrict__ qf,
         const unsigned short* __restrict__ qh, const unsigned short* __restrict__ ql,
         const int* __restrict__ mask,
         unsigned short* __restrict__ outf)
{
    extern __shared__ __align__(16) char asmem[];
    const uint32_t sb = su32(asmem);
    float* lred = (float*)(asmem + A_LR);
    int*   kvm  = (int*)  (asmem + A_KM);

    const int tid = threadIdx.x, lane = tid & 31, wid = tid >> 5;
    const int wm = wid & 3, wn = wid >> 2;
    const int q0 = blockIdx.x * 128;
    const int b  = blockIdx.y >> 3;
    const int h  = blockIdx.y & 7;
    const int RS = 3 * D_;

    // ---- load Q tile [128][64] fp16 ----
    {
        const int r_ = tid >> 3, sg = tid & 7;
        #pragma unroll
        for (int i = 0; i < 4; i++) {
            int r = r_ + 32*i;
            size_t g = (size_t)(b*S_ + q0 + r)*RS + h*DH + sg*8;
            cp16(sb + A_QF + r*AST + sg*16, qf + g);
        }
    }

    // ---- KV tile loader: K fp16, V bf16 hi/lo ----
    auto load_kv = [&](int j, int s) {
        const int r_ = tid >> 3, sg = tid & 7;
        #pragma unroll
        for (int i = 0; i < 2; i++) {
            int r = r_ + 32*i;
            size_t gk = (size_t)(b*S_ + j*64 + r)*RS + D_   + h*DH + sg*8;
            size_t gv = (size_t)(b*S_ + j*64 + r)*RS + 2*D_ + h*DH + sg*8;
            uint32_t so = s*9216 + r*AST + sg*16;
            cp16(sb + A_KF + so, qf + gk);
            cp16(sb + A_VH + so, qh + gv);
            cp16(sb + A_VL + so, ql + gv);
        }
        if (tid < 64) kvm[s*64 + tid] = mask[b*S_ + j*64 + tid];
        asm volatile("cp.async.commit_group;" ::: "memory");
    };
    load_kv(0, 0);

    float oacc[2][4][4];
    #pragma unroll
    for (int i = 0; i < 2; i++)
        #pragma unroll
        for (int j = 0; j < 4; j++)
            #pragma unroll
            for (int k = 0; k < 4; k++) oacc[i][j][k] = 0.f;
    float lreg[2][2] = {{0.f, 0.f}, {0.f, 0.f}};

    const uint32_t lrow = lane & 15;
    const uint32_t lcol = (lane >> 4) * 16;
    const int qr  = lane >> 2;        // row-within-8 for C fragments
    const int cc2 = (lane & 3) * 2;   // col pair base

    for (int j = 0; j < S_/64; j++) {
        const int s = j & 1;
        asm volatile("cp.async.wait_group 0;" ::: "memory");
        __syncthreads();
        if (j + 1 < S_/64) load_kv(j + 1, s ^ 1);

        // ---- S = Q K^T (single-term fp16) ----
        float sacc[2][4][4];
        #pragma unroll
        for (int i = 0; i < 2; i++)
            #pragma unroll
            for (int jj = 0; jj < 4; jj++)
                #pragma unroll
                for (int k = 0; k < 4; k++) sacc[i][jj][k] = 0.f;

        #pragma unroll
        for (int ks = 0; ks < 4; ks++) {           // dh = 64 -> 4 k16 steps
            const uint32_t kb = ks*32 + lcol;
            uint32_t aF[2][4], bF[4][2];
            #pragma unroll
            for (int mt = 0; mt < 2; mt++)
                ldsm4(aF[mt], sb + A_QF + (wm*32 + mt*16 + lrow)*AST + kb);
            #pragma unroll
            for (int g = 0; g < 2; g++) {
                uint32_t t0[4];
                ldsm4(t0, sb + A_KF + s*9216 + (wn*32 + g*16 + lrow)*AST + kb);
                bF[g*2][0]   = t0[0]; bF[g*2][1]   = t0[2];
                bF[g*2+1][0] = t0[1]; bF[g*2+1][1] = t0[3];
            }
            #pragma unroll
            for (int mt = 0; mt < 2; mt++)
                #pragma unroll
                for (int nt = 0; nt < 4; nt++)
                    mma_f16(sacc[mt][nt], aF[mt], bF[nt]);
        }

        // ---- direct exp + mask, register l accumulation, P store (bf16 hi/lo) ----
        #pragma unroll
        for (int nt = 0; nt < 4; nt++) {
            int col = wn*32 + nt*8 + cc2;
            const bool live0 = (kvm[s*64 + col]     != 0);
            const bool live1 = (kvm[s*64 + col + 1] != 0);
            #pragma unroll
            for (int mt = 0; mt < 2; mt++)
                #pragma unroll
                for (int half = 0; half < 2; half++) {
                    float p0 = live0 ? __expf(sacc[mt][nt][2*half])   : 0.f;
                    float p1 = live1 ? __expf(sacc[mt][nt][2*half+1]) : 0.f;
                    lreg[mt][half] += p0 + p1;
                    int row = wm*32 + mt*16 + half*8 + qr;
                    ushort2 hh, ll;
                    bf16_split(p0, hh.x, ll.x);
                    bf16_split(p1, hh.y, ll.y);
                    uint32_t po = row*AST + col*2;
                    *(ushort2*)(asmem + A_PH + po) = hh;
                    *(ushort2*)(asmem + A_PL + po) = ll;
                }
        }
        __syncthreads();

        // ---- O += P V (3-term bf16 split) ----
        #pragma unroll
        for (int ks = 0; ks < 4; ks++) {           // 64 keys -> 4 k16 steps
            const uint32_t kb = ks*32 + lcol;
            uint32_t pHf[2][4], pLf[2][4], vHf[4][2], vLf[4][2];
            #pragma unroll
            for (int mt = 0; mt < 2; mt++) {
                uint32_t ad = sb + (wm*32 + mt*16 + lrow)*AST + kb;
                ldsm4(pHf[mt], ad + A_PH);
                ldsm4(pLf[mt], ad + A_PL);
            }
            #pragma unroll
            for (int g = 0; g < 2; g++) {
                uint32_t va = sb + s*9216
                            + (ks*16 + (lane & 7) + 8*((lane >> 3) & 1))*AST
                            + (wn*32 + g*16 + 8*(lane >> 4))*2;
                uint32_t t0[4], t1[4];
                ldsm4t(t0, va + A_VH);
                ldsm4t(t1, va + A_VL);
                vHf[g*2][0] = t0[0]; vHf[g*2][1] = t0[1];
                vHf[g*2+1][0] = t0[2]; vHf[g*2+1][1] = t0[3];
                vLf[g*2][0] = t1[0]; vLf[g*2][1] = t1[1];
                vLf[g*2+1][0] = t1[2]; vLf[g*2+1][1] = t1[3];
            }
            #pragma unroll
            for (int mt = 0; mt < 2; mt++)
                #pragma unroll
                for (int nt = 0; nt < 4; nt++) {
                    mma_bf16(oacc[mt][nt], pHf[mt], vHf[nt]);
                    mma_bf16(oacc[mt][nt], pHf[mt], vLf[nt]);
                    mma_bf16(oacc[mt][nt], pLf[mt], vHf[nt]);
                }
        }
    }

    // ---- final l reduction: lane group, then across wn via smem ----
    #pragma unroll
    for (int mt = 0; mt < 2; mt++)
        #pragma unroll
        for (int half = 0; half < 2; half++) {
            float v = lreg[mt][half];
            v += __shfl_xor_sync(0xffffffffu, v, 1);
            v += __shfl_xor_sync(0xffffffffu, v, 2);
            lreg[mt][half] = v;
        }
    __syncthreads();   // P buffer reads done; lred region free
    if ((lane & 3) == 0) {
        #pragma unroll
        for (int mt = 0; mt < 2; mt++)
            #pragma unroll
            for (int half = 0; half < 2; half++) {
                int row = wm*32 + mt*16 + half*8 + qr;
                lred[wn*128 + row] = lreg[mt][half];
            }
    }
    __syncthreads();

    // ---- finalize: divide by l, write fp16 ----
    #pragma unroll
    for (int mt = 0; mt < 2; mt++)
        #pragma unroll
        for (int half = 0; half < 2; half++) {
            int row = wm*32 + mt*16 + half*8 + qr;
            float linv = 1.f / (lred[row] + lred[128 + row]);
            size_t base = (size_t)(b*S_ + q0 + row)*D_ + h*DH;
            #pragma unroll
            for (int nt = 0; nt < 4; nt++) {
                int d = wn*32 + nt*8 + cc2;
                float w0 = oacc[mt][nt][2*half]   * linv;
                float w1 = oacc[mt][nt][2*half+1] * linv;
                ushort2 ff; ff.x = f16u(w0); ff.y = f16u(w1);
                *(ushort2*)&outf[base + d] = ff;
            }
        }
}

// ============================================================================
// LayerNorm over last dim (512); optional fp16 side output
// ============================================================================
template<bool EMIT16>
__global__ void __launch_bounds__(256)
ln_kernel(const float* __restrict__ X, const float* __restrict__ g,
          const float* __restrict__ bta, float* __restrict__ Y,
          unsigned short* __restrict__ Yf)
{
    __shared__ float red[32];
    const int row = blockIdx.x;
    const int t = threadIdx.x;
    const int lane = t & 31, w = t >> 5;

    float2 v = ((const float2*)(X + (size_t)row*D_))[t];

    float s = v.x + v.y;
    #pragma unroll
    for (int o = 16; o; o >>= 1) s += __shfl_xor_sync(0xffffffffu, s, o);
    if (lane == 0) red[w] = s;
    __syncthreads();
    if (t < 32) {
        float a = (t < 8) ? red[t] : 0.f;
        #pragma unroll
        for (int o = 4; o; o >>= 1) a += __shfl_xor_sync(0xffffffffu, a, o);
        if (t == 0) red[0] = a;
    }
    __syncthreads();
    const float mu = red[0] * (1.f / D_);
    __syncthreads();

    float d0 = v.x - mu, d1 = v.y - mu;
    float q = d0*d0 + d1*d1;
    #pragma unroll
    for (int o = 16; o; o >>= 1) q += __shfl_xor_sync(0xffffffffu, q, o);
    if (lane == 0) red[w] = q;
    __syncthreads();
    if (t < 32) {
        float a = (t < 8) ? red[t] : 0.f;
        #pragma unroll
        for (int o = 4; o; o >>= 1) a += __shfl_xor_sync(0xffffffffu, a, o);
        if (t == 0) red[0] = a;
    }
    __syncthreads();
    const float var = red[0] * (1.f / D_);
    const float inv = rsqrtf(var + 1e-5f);

    float2 gv = ((const float2*)g)[t];
    float2 bv = ((const float2*)bta)[t];
    float y0 = d0 * inv * gv.x + bv.x;
    float y1 = d1 * inv * gv.y + bv.y;
    float2 o2; o2.x = y0; o2.y = y1;
    ((float2*)(Y + (size_t)row*D_))[t] = o2;
    if (EMIT16) {
        ushort2 ff; ff.x = f16u(y0); ff.y = f16u(y1);
        ((ushort2*)(Yf + (size_t)row*D_))[t] = ff;
    }
}

// ============================================================================
// Host launcher
// ============================================================================
extern "C" void kernel_launch(void* const* d_in, const int* in_sizes, int n_in,
                              void* d_out, int out_size)
{
    const float* x_in  = (const float*)d_in[0];
    const int*   mask  = (const int*)d_in[3];
    const float* Wqkv  = (const float*)d_in[4];
    const float* Wfc   = (const float*)d_in[5];
    const float* bfc   = (const float*)d_in[6];
    const float* ln1g  = (const float*)d_in[7];
    const float* ln1b  = (const float*)d_in[8];
    const float* ln2g  = (const float*)d_in[9];
    const float* ln2b  = (const float*)d_in[10];
    const float* W1    = (const float*)d_in[11];
    const float* b1    = (const float*)d_in[12];
    const float* W2    = (const float*)d_in[13];
    const float* b2    = (const float*)d_in[14];
    float* out = (float*)d_out;

    float *px, *pt;
    unsigned short *pqf, *pqh, *pql, *pxf, *paf, *phf, *pwt;
    cudaGetSymbolAddress((void**)&px,   g_x);
    cudaGetSymbolAddress((void**)&pt,   g_t);
    cudaGetSymbolAddress((void**)&pqf,  g_qf);
    cudaGetSymbolAddress((void**)&pqh,  g_qh);
    cudaGetSymbolAddress((void**)&pql,  g_ql);
    cudaGetSymbolAddress((void**)&pxf,  g_xf);
    cudaGetSymbolAddress((void**)&paf,  g_af);
    cudaGetSymbolAddress((void**)&phf,  g_hf);
    cudaGetSymbolAddress((void**)&pwt,  g_wt);

    const int GSM = 2 * STG_B;   // 40 KB
    cudaFuncSetAttribute(gemm_mma<1>, cudaFuncAttributeMaxDynamicSharedMemorySize, GSM);
    cudaFuncSetAttribute(gemm_mma<2>, cudaFuncAttributeMaxDynamicSharedMemorySize, GSM);
    cudaFuncSetAttribute(gemm_mma<3>, cudaFuncAttributeMaxDynamicSharedMemorySize, GSM);
    cudaFuncSetAttribute(attn_mma, cudaFuncAttributeMaxDynamicSharedMemorySize, A_TOT);

    // weight transpose + fp16 convert (all layers)
    transpose_f16_kernel<<<dim3(1536/32, 512/32, L_), dim3(32,8)>>>(Wqkv, pwt, 512, 1536, OFF_QKV);
    transpose_f16_kernel<<<dim3( 512/32, 512/32, L_), dim3(32,8)>>>(Wfc,  pwt, 512,  512, OFF_FC);
    transpose_f16_kernel<<<dim3(2048/32, 512/32, L_), dim3(32,8)>>>(W1,   pwt, 512, 2048, OFF_W1);
    transpose_f16_kernel<<<dim3( 512/32,2048/32, L_), dim3(32,8)>>>(W2,   pwt, 2048, 512, OFF_W2);

    // position embedding
    pos_scan_kernel<<<B_, S_>>>(mask);
    add_pos_kernel<<<(M_*D_)/256, 256>>>(x_in);

    for (int l = 0; l < L_; l++) {
        const unsigned short* wq = pwt + (size_t)l*WT_L + OFF_QKV;
        const unsigned short* wf = pwt + (size_t)l*WT_L + OFF_FC;
        const unsigned short* w1 = pwt + (size_t)l*WT_L + OFF_W1;
        const unsigned short* w2 = pwt + (size_t)l*WT_L + OFF_W2;

        // qkv = x @ Wqkv: Q,K -> fp16; V -> bf16 hi/lo
        gemm_mma<3><<<dim3(12, 64), 256, GSM>>>(pxf, wq,
            nullptr, nullptr, nullptr, pqf, pqh, pql, 3*D_, D_);

        // attention (QK fp16 single-term, PV bf16 3-term) -> fp16
        attn_mma<<<dim3(S_/128, B_*H_), 256, A_TOT>>>(pqf, pqh, pql, mask, paf);

        // o @ Wfc + bfc + residual(x) -> t ; LN1 -> x (+fp16)
        gemm_mma<1><<<dim3(4, 64), 256, GSM>>>(paf, wf,
            bfc + (size_t)l*D_, px, pt, nullptr, nullptr, nullptr, D_, D_);
        ln_kernel<true><<<M_, 256>>>(pt, ln1g + (size_t)l*D_, ln1b + (size_t)l*D_,
                                     px, pxf);

        // h = relu(x @ W1 + b1) -> fp16
        gemm_mma<2><<<dim3(16, 64), 256, GSM>>>(pxf, w1,
            b1 + (size_t)l*FF_, nullptr, nullptr, nullptr, phf, nullptr, FF_, D_);

        // h @ W2 + b2 + residual(x) -> t ; LN2 -> x (+fp16) or d_out
        gemm_mma<1><<<dim3(4, 64), 256, GSM>>>(phf, w2,
            b2 + (size_t)l*D_, px, pt, nullptr, nullptr, nullptr, D_, FF_);
        if (l == L_-1)
            ln_kernel<false><<<M_, 256>>>(pt, ln2g + (size_t)l*D_, ln2b + (size_t)l*D_,
                                          out, nullptr);
        else
            ln_kernel<true><<<M_, 256>>>(pt, ln2g + (size_t)l*D_, ln2b + (size_t)l*D_,
                                         px, pxf);
    }
}